// round 2
// baseline (speedup 1.0000x reference)
#include <cuda_runtime.h>
#include <math.h>

#define B_   2
#define S_   2048
#define H_   2048
#define NH_  16
#define HD_  128
#define TS_  512
#define ROWS (B_*S_)        // 4096
#define KIDX 460            // sorted index 459 (0-based)

// ---------------- scratch (device globals; no cudaMalloc allowed) ----------
__device__ float g_ts[(size_t)ROWS * TS_];        // ts buffer (reused in-place)
__device__ float g_add[(size_t)ROWS * 4096];      // [q_add | k_add] (v_add == k_add)
__device__ float g_qb[(size_t)ROWS * H_];
__device__ float g_kb[(size_t)ROWS * H_];
__device__ float g_vb[(size_t)ROWS * H_];
__device__ float g_Q[(size_t)ROWS * H_];          // head-major [B,NH,S,HD]
__device__ float g_K[(size_t)ROWS * H_];
__device__ float g_V[(size_t)ROWS * H_];
__device__ float g_attn[(size_t)ROWS * H_];       // [B,S,NH*HD]

// ---------------- generic SGEMM: C[M,N] = A[M,K] @ B[K,N] (+ Add) ----------
// 128x128 block tile, 8x8 per thread, BK=8, 256 threads.
// All M,N multiples of 128; K multiple of 8 (true for every call here).
__global__ __launch_bounds__(256) void sgemm_kernel(
    const float* __restrict__ A, const float* __restrict__ Bm,
    const float* __restrict__ Add, float* __restrict__ C,
    int K, int lda, int ldb, int ldadd, int ldc)
{
    __shared__ float As[8][128];
    __shared__ float Bs[8][128];
    int tid = threadIdx.x;
    int bx = blockIdx.x, by = blockIdx.y;

    int arow = tid >> 1;            // 0..127
    int acol = (tid & 1) << 2;      // 0 or 4
    int brow = tid >> 5;            // 0..7
    int bcol = (tid & 31) << 2;     // 0..124
    int tx = tid & 15, ty = tid >> 4;

    const float* Aptr = A + (size_t)(by * 128 + arow) * lda + acol;
    const float* Bptr = Bm + (size_t)brow * ldb + bx * 128 + bcol;

    float acc[8][8];
    #pragma unroll
    for (int i = 0; i < 8; i++)
        #pragma unroll
        for (int j = 0; j < 8; j++) acc[i][j] = 0.f;

    for (int k0 = 0; k0 < K; k0 += 8) {
        float4 av = *(const float4*)(Aptr + k0);
        float4 bv = *(const float4*)(Bptr + (size_t)k0 * ldb);
        As[acol + 0][arow] = av.x;
        As[acol + 1][arow] = av.y;
        As[acol + 2][arow] = av.z;
        As[acol + 3][arow] = av.w;
        *(float4*)&Bs[brow][bcol] = bv;
        __syncthreads();

        #pragma unroll
        for (int kk = 0; kk < 8; kk++) {
            float4 a0 = *(const float4*)&As[kk][ty * 4];
            float4 a1 = *(const float4*)&As[kk][64 + ty * 4];
            float4 b0 = *(const float4*)&Bs[kk][tx * 4];
            float4 b1 = *(const float4*)&Bs[kk][64 + tx * 4];
            float a[8] = {a0.x, a0.y, a0.z, a0.w, a1.x, a1.y, a1.z, a1.w};
            float b[8] = {b0.x, b0.y, b0.z, b0.w, b1.x, b1.y, b1.z, b1.w};
            #pragma unroll
            for (int i = 0; i < 8; i++)
                #pragma unroll
                for (int j = 0; j < 8; j++)
                    acc[i][j] += a[i] * b[j];
        }
        __syncthreads();
    }

    #pragma unroll
    for (int i = 0; i < 8; i++) {
        int row = by * 128 + ((i < 4) ? (ty * 4 + i) : (64 + ty * 4 + i - 4));
        #pragma unroll
        for (int jh = 0; jh < 2; jh++) {
            int col = bx * 128 + (jh ? (64 + tx * 4) : (tx * 4));
            float4 r = make_float4(acc[i][jh * 4 + 0], acc[i][jh * 4 + 1],
                                   acc[i][jh * 4 + 2], acc[i][jh * 4 + 3]);
            if (Add) {
                float4 ad = *(const float4*)&Add[(size_t)row * ldadd + col];
                r.x += ad.x; r.y += ad.y; r.z += ad.z; r.w += ad.w;
            }
            *(float4*)&C[(size_t)row * ldc + col] = r;
        }
    }
}

// -------- blend + rmsnorm + exact k-th order statistic + relu-shift --------
// one row (512 elems) per 512-thread block; bitonic sort in smem (exact).
__global__ __launch_bounds__(512) void ts_rowops_kernel(
    const float* __restrict__ last, const float* __restrict__ w, float* __restrict__ ts)
{
    __shared__ float sv[512];
    __shared__ float rbuf[512];
    int row = blockIdx.x;
    int j = threadIdx.x;
    size_t idx = (size_t)row * TS_ + j;

    float x = 0.5f * ts[idx] + 0.5f * last[idx];      // (1-ALPHA)*ts + ALPHA*last
    rbuf[j] = x * x;
    __syncthreads();
    #pragma unroll
    for (int s2 = 256; s2 > 0; s2 >>= 1) {
        if (j < s2) rbuf[j] += rbuf[j + s2];
        __syncthreads();
    }
    float var = rbuf[0] * (1.f / 512.f);
    float y = x * rsqrtf(var + 1e-6f) * w[j];
    sv[j] = y;
    __syncthreads();

    // bitonic sort ascending, 512 elements
    for (int k = 2; k <= 512; k <<= 1) {
        for (int jj = k >> 1; jj > 0; jj >>= 1) {
            int ixj = j ^ jj;
            if (ixj > j) {
                float a = sv[j], b = sv[ixj];
                bool asc = ((j & k) == 0);
                if (asc ? (a > b) : (a < b)) { sv[j] = b; sv[ixj] = a; }
            }
            __syncthreads();
        }
    }
    float kth = sv[KIDX - 1];
    ts[idx] = fmaxf(y - kth, 0.f);
}

// ---------------- RoPE + transpose to head-major [B,NH,S,HD] --------------
__global__ void rope_transpose_kernel(
    const float* __restrict__ qb, const float* __restrict__ kb, const float* __restrict__ vb,
    float* __restrict__ Q, float* __restrict__ Ko, float* __restrict__ V)
{
    int i = blockIdx.x * blockDim.x + threadIdx.x;
    if (i >= ROWS * NH_ * 64) return;
    int d = i & 63;
    int h = (i >> 6) & (NH_ - 1);
    int row = i >> 10;              // 0..4095
    int b = row >> 11;              // row / 2048
    int s = row & (S_ - 1);

    // inv freq in double to stay within ~1 ulp of numpy's fp32 table
    float inv = (float)exp(-(double)d * (9.210340371976184 / 64.0));
    float ang = (float)s * inv;     // fp32 product, matching np.outer in fp32
    float cs, sn;
    sincosf(ang, &sn, &cs);         // FIXED: sincosf writes SIN first, COS second

    size_t src = (size_t)row * H_ + h * HD_ + d;
    float q0 = qb[src], q1 = qb[src + 64];
    float k0 = kb[src], k1 = kb[src + 64];
    size_t dst = ((size_t)(b * NH_ + h) * S_ + s) * HD_ + d;
    Q[dst]       = q0 * cs - q1 * sn;
    Q[dst + 64]  = q1 * cs + q0 * sn;
    Ko[dst]      = k0 * cs - k1 * sn;
    Ko[dst + 64] = k1 * cs + k0 * sn;
    V[dst]       = vb[src];
    V[dst + 64]  = vb[src + 64];
}

// ---------------- flash attention (fp32, causal, online softmax) ----------
#define FBM 64
#define FBN 64
#define FLASH_SMEM ((FBM*HD_ + FBN*HD_ + FBN*HD_ + FBM*FBN) * 4)   // 112 KB

__global__ __launch_bounds__(256) void flash_kernel(
    const float* __restrict__ Qg, const float* __restrict__ Kg,
    const float* __restrict__ Vg, float* __restrict__ Og)
{
    extern __shared__ float sm[];
    float* Qs = sm;                     // FBM x HD
    float* Ks = Qs + FBM * HD_;         // FBN x HD
    float* Vs = Ks + FBN * HD_;         // FBN x HD
    float* Ps = Vs + FBN * HD_;         // FBM x FBN

    int qt = blockIdx.x;
    int bh = blockIdx.y;
    int tid = threadIdx.x;

    const float* Qbase = Qg + ((size_t)bh * S_ + (size_t)qt * FBM) * HD_;
    const float* Kbase = Kg + (size_t)bh * S_ * HD_;
    const float* Vbase = Vg + (size_t)bh * S_ * HD_;

    for (int i = tid; i < FBM * HD_ / 4; i += 256)
        ((float4*)Qs)[i] = ((const float4*)Qbase)[i];

    int ty = tid >> 4, tx = tid & 15;
    int r0 = ty * 4, c0 = tx * 4;

    float m_i[4], l_i[4], acc[4][8];
    #pragma unroll
    for (int i = 0; i < 4; i++) {
        m_i[i] = -INFINITY; l_i[i] = 0.f;
        #pragma unroll
        for (int j = 0; j < 8; j++) acc[i][j] = 0.f;
    }
    const float scale = 0.08838834764831845f;   // 1/sqrt(128)

    for (int kt = 0; kt <= qt; ++kt) {
        __syncthreads();
        const float4* Ksrc = (const float4*)(Kbase + (size_t)kt * FBN * HD_);
        const float4* Vsrc = (const float4*)(Vbase + (size_t)kt * FBN * HD_);
        for (int i = tid; i < FBN * HD_ / 4; i += 256) {
            ((float4*)Ks)[i] = Ksrc[i];
            ((float4*)Vs)[i] = Vsrc[i];
        }
        __syncthreads();

        // S = Q K^T  (4x4 per thread)
        float s[4][4];
        #pragma unroll
        for (int i = 0; i < 4; i++)
            #pragma unroll
            for (int j = 0; j < 4; j++) s[i][j] = 0.f;

        for (int d0 = 0; d0 < HD_; d0 += 4) {
            float4 qv[4], kv[4];
            #pragma unroll
            for (int i = 0; i < 4; i++) qv[i] = *(const float4*)&Qs[(r0 + i) * HD_ + d0];
            #pragma unroll
            for (int j = 0; j < 4; j++) kv[j] = *(const float4*)&Ks[(c0 + j) * HD_ + d0];
            #pragma unroll
            for (int i = 0; i < 4; i++)
                #pragma unroll
                for (int j = 0; j < 4; j++)
                    s[i][j] += qv[i].x * kv[j].x + qv[i].y * kv[j].y +
                               qv[i].z * kv[j].z + qv[i].w * kv[j].w;
        }

        if (kt == qt) {
            #pragma unroll
            for (int i = 0; i < 4; i++)
                #pragma unroll
                for (int j = 0; j < 4; j++)
                    s[i][j] = (c0 + j <= r0 + i) ? s[i][j] * scale : -1e30f;
        } else {
            #pragma unroll
            for (int i = 0; i < 4; i++)
                #pragma unroll
                for (int j = 0; j < 4; j++) s[i][j] *= scale;
        }

        // online softmax per row (16 tx lanes per row; 16-group aligned in warp)
        #pragma unroll
        for (int i = 0; i < 4; i++) {
            float rm = fmaxf(fmaxf(s[i][0], s[i][1]), fmaxf(s[i][2], s[i][3]));
            #pragma unroll
            for (int off = 8; off >= 1; off >>= 1)
                rm = fmaxf(rm, __shfl_xor_sync(0xffffffffu, rm, off));
            float mnew = fmaxf(m_i[i], rm);
            float corr = __expf(m_i[i] - mnew);
            float rs = 0.f;
            #pragma unroll
            for (int j = 0; j < 4; j++) {
                float p = __expf(s[i][j] - mnew);   // masked -1e30 -> exactly 0
                Ps[(r0 + i) * FBN + c0 + j] = p;
                rs += p;
            }
            #pragma unroll
            for (int off = 8; off >= 1; off >>= 1)
                rs += __shfl_xor_sync(0xffffffffu, rs, off);
            l_i[i] = l_i[i] * corr + rs;
            m_i[i] = mnew;
            #pragma unroll
            for (int j = 0; j < 8; j++) acc[i][j] *= corr;
        }
        __syncthreads();

        // O += P @ V   (thread covers rows r0..r0+3, cols tx*8..tx*8+7)
        int vc = tx * 8;
        for (int k = 0; k < FBN; k++) {
            float4 v0 = *(const float4*)&Vs[k * HD_ + vc];
            float4 v1 = *(const float4*)&Vs[k * HD_ + vc + 4];
            #pragma unroll
            for (int i = 0; i < 4; i++) {
                float p = Ps[(r0 + i) * FBN + k];
                acc[i][0] += p * v0.x; acc[i][1] += p * v0.y;
                acc[i][2] += p * v0.z; acc[i][3] += p * v0.w;
                acc[i][4] += p * v1.x; acc[i][5] += p * v1.y;
                acc[i][6] += p * v1.z; acc[i][7] += p * v1.w;
            }
        }
    }

    // epilogue: O /= l, write to [B,S,NH*HD]
    int b = bh >> 4, h = bh & (NH_ - 1);
    #pragma unroll
    for (int i = 0; i < 4; i++) {
        float rl = 1.f / l_i[i];
        int srow = qt * FBM + r0 + i;
        float* dst = Og + ((size_t)(b * S_ + srow)) * H_ + h * HD_ + tx * 8;
        ((float4*)dst)[0] = make_float4(acc[i][0] * rl, acc[i][1] * rl, acc[i][2] * rl, acc[i][3] * rl);
        ((float4*)dst)[1] = make_float4(acc[i][4] * rl, acc[i][5] * rl, acc[i][6] * rl, acc[i][7] * rl);
    }
}

// ---------------------------------------------------------------------------
extern "C" void kernel_launch(void* const* d_in, const int* in_sizes, int n_in,
                              void* d_out, int out_size)
{
    const float* hidden = (const float*)d_in[0];
    const float* lastts = (const float*)d_in[1];
    const float* Wq     = (const float*)d_in[2];
    const float* Wk     = (const float*)d_in[3];
    const float* Wv     = (const float*)d_in[4];
    const float* Wo     = (const float*)d_in[5];
    const float* Wts    = (const float*)d_in[6];
    const float* tsw    = (const float*)d_in[7];
    const float* Worig  = (const float*)d_in[8];
    float* out = (float*)d_out;

    float *ts, *add, *qb, *kb, *vb, *Q, *K, *V, *attn;
    cudaGetSymbolAddress((void**)&ts,   g_ts);
    cudaGetSymbolAddress((void**)&add,  g_add);
    cudaGetSymbolAddress((void**)&qb,   g_qb);
    cudaGetSymbolAddress((void**)&kb,   g_kb);
    cudaGetSymbolAddress((void**)&vb,   g_vb);
    cudaGetSymbolAddress((void**)&Q,    g_Q);
    cudaGetSymbolAddress((void**)&K,    g_K);
    cudaGetSymbolAddress((void**)&V,    g_V);
    cudaGetSymbolAddress((void**)&attn, g_attn);

    // 1) ts = hidden @ Wts                    [4096,512]
    sgemm_kernel<<<dim3(TS_/128, ROWS/128), 256>>>(hidden, Wts, nullptr, ts,
                                                   H_, H_, TS_, 0, TS_);
    // 2) blend + rmsnorm + kth + relu (in place)
    ts_rowops_kernel<<<ROWS, 512>>>(lastts, tsw, ts);

    // 3) add = ts @ Worig[:, :4096]   (third slice of Worig is unused!)
    sgemm_kernel<<<dim3(4096/128, ROWS/128), 256>>>(ts, Worig, nullptr, add,
                                                    TS_, TS_, 3*H_, 0, 4096);

    // 4) q/k/v = hidden @ W* + add-slice
    dim3 gq(H_/128, ROWS/128);
    sgemm_kernel<<<gq, 256>>>(hidden, Wq, add,        qb, H_, H_, H_, 4096, H_);
    sgemm_kernel<<<gq, 256>>>(hidden, Wk, add + 2048, kb, H_, H_, H_, 4096, H_);
    sgemm_kernel<<<gq, 256>>>(hidden, Wv, add + 2048, vb, H_, H_, H_, 4096, H_);

    // 5) RoPE + transpose to head-major
    int tot = ROWS * NH_ * 64;
    rope_transpose_kernel<<<(tot + 255) / 256, 256>>>(qb, kb, vb, Q, K, V);

    // 6) causal flash attention
    cudaFuncSetAttribute(flash_kernel, cudaFuncAttributeMaxDynamicSharedMemorySize, FLASH_SMEM);
    flash_kernel<<<dim3(S_/FBM, B_*NH_), 256, FLASH_SMEM>>>(Q, K, V, attn);

    // 7) out = attn @ Wo
    sgemm_kernel<<<gq, 256>>>(attn, Wo, nullptr, out, H_, H_, H_, 0, H_);
}

// round 3
// speedup vs baseline: 1.0494x; 1.0494x over previous
#include <cuda_runtime.h>
#include <math.h>

#define B_   2
#define S_   2048
#define H_   2048
#define NH_  16
#define HD_  128
#define TS_  512
#define ROWS (B_*S_)        // 4096
#define KIDX 460            // sorted index 459 (0-based)

typedef unsigned long long u64;

// ------------------------- f32x2 packed helpers ---------------------------
__device__ __forceinline__ u64 pack2(float lo, float hi) {
    u64 r; asm("mov.b64 %0,{%1,%2};" : "=l"(r) : "f"(lo), "f"(hi)); return r;
}
__device__ __forceinline__ u64 dup2(float x) { return pack2(x, x); }
__device__ __forceinline__ u64 fma2(u64 a, u64 b, u64 c) {
    u64 d; asm("fma.rn.f32x2 %0,%1,%2,%3;" : "=l"(d) : "l"(a), "l"(b), "l"(c)); return d;
}
__device__ __forceinline__ u64 add2(u64 a, u64 b) {
    u64 d; asm("add.rn.f32x2 %0,%1,%2;" : "=l"(d) : "l"(a), "l"(b)); return d;
}
__device__ __forceinline__ u64 mul2(u64 a, u64 b) {
    u64 d; asm("mul.rn.f32x2 %0,%1,%2;" : "=l"(d) : "l"(a), "l"(b)); return d;
}
__device__ __forceinline__ void unpack2(u64 v, float& lo, float& hi) {
    asm("mov.b64 {%0,%1},%2;" : "=f"(lo), "=f"(hi) : "l"(v));
}

// ---------------- scratch (device globals; no cudaMalloc allowed) ----------
__device__ float g_ts[(size_t)ROWS * TS_];
__device__ float g_add[(size_t)ROWS * 4096];      // [q_add | k_add] (v_add == k_add)
__device__ float g_qb[(size_t)ROWS * H_];
__device__ float g_kb[(size_t)ROWS * H_];
__device__ float g_vb[(size_t)ROWS * H_];
__device__ float g_Q[(size_t)ROWS * H_];          // head-major [B,NH,S,HD]
__device__ float g_K[(size_t)ROWS * H_];
__device__ float g_V[(size_t)ROWS * H_];
__device__ float g_attn[(size_t)ROWS * H_];       // [B,S,NH*HD]

// ---------------- generic SGEMM: C[M,N] = A[M,K] @ B[K,N] (+ Add) ----------
// 128x128 tile, 8x8 per thread via f32x2, BK=8, 256 threads, double-buffered.
__device__ __forceinline__ void gemm_compute(
    const float (*As8)[128], const float (*Bs8)[128],
    int tx, int ty, u64 acc2[8][4])
{
    #pragma unroll
    for (int kk = 0; kk < 8; kk++) {
        ulonglong2 b0 = *(const ulonglong2*)&Bs8[kk][tx * 4];
        ulonglong2 b1 = *(const ulonglong2*)&Bs8[kk][64 + tx * 4];
        float4 a0 = *(const float4*)&As8[kk][ty * 4];
        float4 a1 = *(const float4*)&As8[kk][64 + ty * 4];
        u64 bb0 = b0.x, bb1 = b0.y, bb2 = b1.x, bb3 = b1.y;
        float aa[8] = {a0.x, a0.y, a0.z, a0.w, a1.x, a1.y, a1.z, a1.w};
        #pragma unroll
        for (int i = 0; i < 8; i++) {
            u64 ad = dup2(aa[i]);
            acc2[i][0] = fma2(ad, bb0, acc2[i][0]);
            acc2[i][1] = fma2(ad, bb1, acc2[i][1]);
            acc2[i][2] = fma2(ad, bb2, acc2[i][2]);
            acc2[i][3] = fma2(ad, bb3, acc2[i][3]);
        }
    }
}

__global__ __launch_bounds__(256) void sgemm_kernel(
    const float* __restrict__ A, const float* __restrict__ Bm,
    const float* __restrict__ Add, float* __restrict__ C,
    int K, int lda, int ldb, int ldadd, int ldc)
{
    __shared__ float As[2][8][128];
    __shared__ float Bs[2][8][128];
    int tid = threadIdx.x;
    int bx = blockIdx.x, by = blockIdx.y;

    int arow = tid >> 1;            // 0..127
    int acol = (tid & 1) << 2;      // 0 or 4
    int brow = tid >> 5;            // 0..7
    int bcol = (tid & 31) << 2;     // 0..124
    int tx = tid & 15, ty = tid >> 4;

    const float* Aptr = A + (size_t)(by * 128 + arow) * lda + acol;
    const float* Bptr = Bm + (size_t)brow * ldb + bx * 128 + bcol;

    u64 acc2[8][4];
    #pragma unroll
    for (int i = 0; i < 8; i++)
        #pragma unroll
        for (int j = 0; j < 4; j++) acc2[i][j] = 0ull;   // (0.f,0.f)

    // stage 0
    float4 pa = *(const float4*)(Aptr);
    float4 pb = *(const float4*)(Bptr);
    As[0][acol + 0][arow] = pa.x;
    As[0][acol + 1][arow] = pa.y;
    As[0][acol + 2][arow] = pa.z;
    As[0][acol + 3][arow] = pa.w;
    *(float4*)&Bs[0][brow][bcol] = pb;
    __syncthreads();

    int cur = 0;
    for (int k0 = 8; k0 < K; k0 += 8) {
        pa = *(const float4*)(Aptr + k0);
        pb = *(const float4*)(Bptr + (size_t)k0 * ldb);
        gemm_compute(As[cur], Bs[cur], tx, ty, acc2);
        int nxt = cur ^ 1;
        As[nxt][acol + 0][arow] = pa.x;
        As[nxt][acol + 1][arow] = pa.y;
        As[nxt][acol + 2][arow] = pa.z;
        As[nxt][acol + 3][arow] = pa.w;
        *(float4*)&Bs[nxt][brow][bcol] = pb;
        __syncthreads();
        cur = nxt;
    }
    gemm_compute(As[cur], Bs[cur], tx, ty, acc2);

    #pragma unroll
    for (int i = 0; i < 8; i++) {
        int row = by * 128 + ((i < 4) ? (ty * 4 + i) : (64 + ty * 4 + i - 4));
        #pragma unroll
        for (int half = 0; half < 2; half++) {
            int col = bx * 128 + half * 64 + tx * 4;
            u64 r0 = acc2[i][half * 2 + 0];
            u64 r1 = acc2[i][half * 2 + 1];
            if (Add) {
                ulonglong2 ad = *(const ulonglong2*)&Add[(size_t)row * ldadd + col];
                r0 = add2(r0, ad.x);
                r1 = add2(r1, ad.y);
            }
            ulonglong2 st; st.x = r0; st.y = r1;
            *(ulonglong2*)&C[(size_t)row * ldc + col] = st;
        }
    }
}

// -------- blend + rmsnorm + exact k-th order statistic + relu-shift --------
__global__ __launch_bounds__(512) void ts_rowops_kernel(
    const float* __restrict__ last, const float* __restrict__ w, float* __restrict__ ts)
{
    __shared__ float sv[512];
    __shared__ float rbuf[512];
    int row = blockIdx.x;
    int j = threadIdx.x;
    size_t idx = (size_t)row * TS_ + j;

    float x = 0.5f * ts[idx] + 0.5f * last[idx];
    rbuf[j] = x * x;
    __syncthreads();
    #pragma unroll
    for (int s2 = 256; s2 > 0; s2 >>= 1) {
        if (j < s2) rbuf[j] += rbuf[j + s2];
        __syncthreads();
    }
    float var = rbuf[0] * (1.f / 512.f);
    float y = x * rsqrtf(var + 1e-6f) * w[j];
    sv[j] = y;
    __syncthreads();

    for (int k = 2; k <= 512; k <<= 1) {
        for (int jj = k >> 1; jj > 0; jj >>= 1) {
            int ixj = j ^ jj;
            if (ixj > j) {
                float a = sv[j], b = sv[ixj];
                bool asc = ((j & k) == 0);
                if (asc ? (a > b) : (a < b)) { sv[j] = b; sv[ixj] = a; }
            }
            __syncthreads();
        }
    }
    float kth = sv[KIDX - 1];
    ts[idx] = fmaxf(y - kth, 0.f);
}

// ---------------- RoPE + transpose to head-major [B,NH,S,HD] --------------
__global__ void rope_transpose_kernel(
    const float* __restrict__ qb, const float* __restrict__ kb, const float* __restrict__ vb,
    float* __restrict__ Q, float* __restrict__ Ko, float* __restrict__ V)
{
    int i = blockIdx.x * blockDim.x + threadIdx.x;
    if (i >= ROWS * NH_ * 64) return;
    int d = i & 63;
    int h = (i >> 6) & (NH_ - 1);
    int row = i >> 10;
    int b = row >> 11;
    int s = row & (S_ - 1);

    float inv = (float)exp(-(double)d * (9.210340371976184 / 64.0));
    float ang = (float)s * inv;
    float cs, sn;
    sincosf(ang, &sn, &cs);         // sin first, cos second

    size_t src = (size_t)row * H_ + h * HD_ + d;
    float q0 = qb[src], q1 = qb[src + 64];
    float k0 = kb[src], k1 = kb[src + 64];
    size_t dst = ((size_t)(b * NH_ + h) * S_ + s) * HD_ + d;
    Q[dst]       = q0 * cs - q1 * sn;
    Q[dst + 64]  = q1 * cs + q0 * sn;
    Ko[dst]      = k0 * cs - k1 * sn;
    Ko[dst + 64] = k1 * cs + k0 * sn;
    V[dst]       = vb[src];
    V[dst + 64]  = vb[src + 64];
}

// ---------------- flash attention (fp32, causal, online softmax) ----------
#define FBM 64
#define FBN 64
#define PS_LD 68
#define FLASH_SMEM ((FBM*HD_ + FBN*HD_ + FBN*HD_ + FBM*PS_LD) * 4)

__global__ __launch_bounds__(256) void flash_kernel(
    const float* __restrict__ Qg, const float* __restrict__ Kg,
    const float* __restrict__ Vg, float* __restrict__ Og)
{
    extern __shared__ float sm[];
    float* Qs = sm;                     // FBM x HD
    float* Ks = Qs + FBM * HD_;         // FBN x HD
    float* Vs = Ks + FBN * HD_;         // FBN x HD
    float* Ps = Vs + FBN * HD_;         // FBM x PS_LD

    int qt = blockIdx.x;
    int bh = blockIdx.y;
    int tid = threadIdx.x;

    const float* Qbase = Qg + ((size_t)bh * S_ + (size_t)qt * FBM) * HD_;
    const float* Kbase = Kg + (size_t)bh * S_ * HD_;
    const float* Vbase = Vg + (size_t)bh * S_ * HD_;

    for (int i = tid; i < FBM * HD_ / 4; i += 256)
        ((float4*)Qs)[i] = ((const float4*)Qbase)[i];

    int ty = tid >> 4, tx = tid & 15;
    int r0 = ty * 4, c0 = tx * 4;

    float m_i[4], l_i[4];
    u64 acc2[4][4];                 // rows r0..r0+3, cols tx*8..tx*8+7 (4 pairs)
    #pragma unroll
    for (int i = 0; i < 4; i++) {
        m_i[i] = -INFINITY; l_i[i] = 0.f;
        #pragma unroll
        for (int j = 0; j < 4; j++) acc2[i][j] = 0ull;
    }
    const float scale = 0.08838834764831845f;   // 1/sqrt(128)

    for (int kt = 0; kt <= qt; ++kt) {
        __syncthreads();
        const float4* Ksrc = (const float4*)(Kbase + (size_t)kt * FBN * HD_);
        const float4* Vsrc = (const float4*)(Vbase + (size_t)kt * FBN * HD_);
        for (int i = tid; i < FBN * HD_ / 4; i += 256) {
            ((float4*)Ks)[i] = Ksrc[i];
            ((float4*)Vs)[i] = Vsrc[i];
        }
        __syncthreads();

        // S = Q K^T, packed along d (two partial sums per accumulator)
        u64 s2[4][4];
        #pragma unroll
        for (int i = 0; i < 4; i++)
            #pragma unroll
            for (int j = 0; j < 4; j++) s2[i][j] = 0ull;

        for (int d0 = 0; d0 < HD_; d0 += 4) {
            ulonglong2 qv[4], kv[4];
            #pragma unroll
            for (int i = 0; i < 4; i++) qv[i] = *(const ulonglong2*)&Qs[(r0 + i) * HD_ + d0];
            #pragma unroll
            for (int j = 0; j < 4; j++) kv[j] = *(const ulonglong2*)&Ks[(c0 + j) * HD_ + d0];
            #pragma unroll
            for (int i = 0; i < 4; i++)
                #pragma unroll
                for (int j = 0; j < 4; j++) {
                    s2[i][j] = fma2(qv[i].x, kv[j].x, s2[i][j]);
                    s2[i][j] = fma2(qv[i].y, kv[j].y, s2[i][j]);
                }
        }

        float s[4][4];
        #pragma unroll
        for (int i = 0; i < 4; i++)
            #pragma unroll
            for (int j = 0; j < 4; j++) {
                float lo, hi; unpack2(s2[i][j], lo, hi);
                s[i][j] = lo + hi;
            }

        if (kt == qt) {
            #pragma unroll
            for (int i = 0; i < 4; i++)
                #pragma unroll
                for (int j = 0; j < 4; j++)
                    s[i][j] = (c0 + j <= r0 + i) ? s[i][j] * scale : -1e30f;
        } else {
            #pragma unroll
            for (int i = 0; i < 4; i++)
                #pragma unroll
                for (int j = 0; j < 4; j++) s[i][j] *= scale;
        }

        // online softmax per row
        #pragma unroll
        for (int i = 0; i < 4; i++) {
            float rm = fmaxf(fmaxf(s[i][0], s[i][1]), fmaxf(s[i][2], s[i][3]));
            #pragma unroll
            for (int off = 8; off >= 1; off >>= 1)
                rm = fmaxf(rm, __shfl_xor_sync(0xffffffffu, rm, off));
            float mnew = fmaxf(m_i[i], rm);
            float corr = __expf(m_i[i] - mnew);
            float rs = 0.f;
            #pragma unroll
            for (int j = 0; j < 4; j++) {
                float p = __expf(s[i][j] - mnew);
                Ps[(r0 + i) * PS_LD + c0 + j] = p;
                rs += p;
            }
            #pragma unroll
            for (int off = 8; off >= 1; off >>= 1)
                rs += __shfl_xor_sync(0xffffffffu, rs, off);
            l_i[i] = l_i[i] * corr + rs;
            m_i[i] = mnew;
            u64 cd = dup2(corr);
            #pragma unroll
            for (int j = 0; j < 4; j++) acc2[i][j] = mul2(acc2[i][j], cd);
        }
        __syncthreads();

        // O += P @ V, packed along output columns
        int vc = tx * 8;
        #pragma unroll 4
        for (int k = 0; k < FBN; k++) {
            ulonglong2 v0 = *(const ulonglong2*)&Vs[k * HD_ + vc];
            ulonglong2 v1 = *(const ulonglong2*)&Vs[k * HD_ + vc + 4];
            u64 vv0 = v0.x, vv1 = v0.y, vv2 = v1.x, vv3 = v1.y;
            #pragma unroll
            for (int i = 0; i < 4; i++) {
                u64 pd = dup2(Ps[(r0 + i) * PS_LD + k]);
                acc2[i][0] = fma2(pd, vv0, acc2[i][0]);
                acc2[i][1] = fma2(pd, vv1, acc2[i][1]);
                acc2[i][2] = fma2(pd, vv2, acc2[i][2]);
                acc2[i][3] = fma2(pd, vv3, acc2[i][3]);
            }
        }
    }

    // epilogue: O /= l, write to [B,S,NH*HD]
    int b = bh >> 4, h = bh & (NH_ - 1);
    #pragma unroll
    for (int i = 0; i < 4; i++) {
        u64 rl = dup2(1.f / l_i[i]);
        int srow = qt * FBM + r0 + i;
        float* dst = Og + ((size_t)(b * S_ + srow)) * H_ + h * HD_ + tx * 8;
        ulonglong2 st0, st1;
        st0.x = mul2(acc2[i][0], rl); st0.y = mul2(acc2[i][1], rl);
        st1.x = mul2(acc2[i][2], rl); st1.y = mul2(acc2[i][3], rl);
        ((ulonglong2*)dst)[0] = st0;
        ((ulonglong2*)dst)[1] = st1;
    }
}

// ---------------------------------------------------------------------------
extern "C" void kernel_launch(void* const* d_in, const int* in_sizes, int n_in,
                              void* d_out, int out_size)
{
    const float* hidden = (const float*)d_in[0];
    const float* lastts = (const float*)d_in[1];
    const float* Wq     = (const float*)d_in[2];
    const float* Wk     = (const float*)d_in[3];
    const float* Wv     = (const float*)d_in[4];
    const float* Wo     = (const float*)d_in[5];
    const float* Wts    = (const float*)d_in[6];
    const float* tsw    = (const float*)d_in[7];
    const float* Worig  = (const float*)d_in[8];
    float* out = (float*)d_out;

    float *ts, *add, *qb, *kb, *vb, *Q, *K, *V, *attn;
    cudaGetSymbolAddress((void**)&ts,   g_ts);
    cudaGetSymbolAddress((void**)&add,  g_add);
    cudaGetSymbolAddress((void**)&qb,   g_qb);
    cudaGetSymbolAddress((void**)&kb,   g_kb);
    cudaGetSymbolAddress((void**)&vb,   g_vb);
    cudaGetSymbolAddress((void**)&Q,    g_Q);
    cudaGetSymbolAddress((void**)&K,    g_K);
    cudaGetSymbolAddress((void**)&V,    g_V);
    cudaGetSymbolAddress((void**)&attn, g_attn);

    // 1) ts = hidden @ Wts
    sgemm_kernel<<<dim3(TS_/128, ROWS/128), 256>>>(hidden, Wts, nullptr, ts,
                                                   H_, H_, TS_, 0, TS_);
    // 2) blend + rmsnorm + kth + relu (in place)
    ts_rowops_kernel<<<ROWS, 512>>>(lastts, tsw, ts);

    // 3) add = ts @ Worig[:, :4096]
    sgemm_kernel<<<dim3(4096/128, ROWS/128), 256>>>(ts, Worig, nullptr, add,
                                                    TS_, TS_, 3*H_, 0, 4096);

    // 4) q/k/v = hidden @ W* + add-slice
    dim3 gq(H_/128, ROWS/128);
    sgemm_kernel<<<gq, 256>>>(hidden, Wq, add,        qb, H_, H_, H_, 4096, H_);
    sgemm_kernel<<<gq, 256>>>(hidden, Wk, add + 2048, kb, H_, H_, H_, 4096, H_);
    sgemm_kernel<<<gq, 256>>>(hidden, Wv, add + 2048, vb, H_, H_, H_, 4096, H_);

    // 5) RoPE + transpose
    int tot = ROWS * NH_ * 64;
    rope_transpose_kernel<<<(tot + 255) / 256, 256>>>(qb, kb, vb, Q, K, V);

    // 6) causal flash attention
    cudaFuncSetAttribute(flash_kernel, cudaFuncAttributeMaxDynamicSharedMemorySize, FLASH_SMEM);
    flash_kernel<<<dim3(S_/FBM, B_*NH_), 256, FLASH_SMEM>>>(Q, K, V, attn);

    // 7) out = attn @ Wo
    sgemm_kernel<<<gq, 256>>>(attn, Wo, nullptr, out, H_, H_, H_, 0, H_);
}

// round 5
// speedup vs baseline: 1.2846x; 1.2242x over previous
#include <cuda_runtime.h>
#include <cuda_bf16.h>
#include <math.h>
#include <stdint.h>

#define B_   2
#define S_   2048
#define H_   2048
#define NH_  16
#define HD_  128
#define TS_  512
#define ROWS (B_*S_)        // 4096
#define KIDX 460

typedef unsigned long long u64;

// ------------------------- f32x2 packed helpers (flash) --------------------
__device__ __forceinline__ u64 pack2(float lo, float hi) {
    u64 r; asm("mov.b64 %0,{%1,%2};" : "=l"(r) : "f"(lo), "f"(hi)); return r;
}
__device__ __forceinline__ u64 dup2(float x) { return pack2(x, x); }
__device__ __forceinline__ u64 fma2(u64 a, u64 b, u64 c) {
    u64 d; asm("fma.rn.f32x2 %0,%1,%2,%3;" : "=l"(d) : "l"(a), "l"(b), "l"(c)); return d;
}
__device__ __forceinline__ u64 mul2(u64 a, u64 b) {
    u64 d; asm("mul.rn.f32x2 %0,%1,%2;" : "=l"(d) : "l"(a), "l"(b)); return d;
}
__device__ __forceinline__ void unpack2(u64 v, float& lo, float& hi) {
    asm("mov.b64 {%0,%1},%2;" : "=f"(lo), "=f"(hi) : "l"(v));
}

// ------------------------- mma.sync helpers (baseline PTX, no 'a') ---------
__device__ __forceinline__ uint32_t smem_u32(const void* p) {
    uint32_t a;
    asm("{ .reg .u64 t; cvta.to.shared.u64 t,%1; cvt.u32.u64 %0,t; }" : "=r"(a) : "l"(p));
    return a;
}
__device__ __forceinline__ void ldsm4(uint32_t* r, uint32_t addr) {
    asm volatile("ldmatrix.sync.aligned.m8n8.x4.shared.b16 {%0,%1,%2,%3},[%4];"
        : "=r"(r[0]), "=r"(r[1]), "=r"(r[2]), "=r"(r[3]) : "r"(addr));
}
__device__ __forceinline__ void ldsm2(uint32_t* r, uint32_t addr) {
    asm volatile("ldmatrix.sync.aligned.m8n8.x2.shared.b16 {%0,%1},[%2];"
        : "=r"(r[0]), "=r"(r[1]) : "r"(addr));
}
__device__ __forceinline__ void mma16816(float* c, const uint32_t* a, const uint32_t* b) {
    asm volatile(
        "mma.sync.aligned.m16n8k16.row.col.f32.bf16.bf16.f32 "
        "{%0,%1,%2,%3},{%4,%5,%6,%7},{%8,%9},{%0,%1,%2,%3};"
        : "+f"(c[0]), "+f"(c[1]), "+f"(c[2]), "+f"(c[3])
        : "r"(a[0]), "r"(a[1]), "r"(a[2]), "r"(a[3]), "r"(b[0]), "r"(b[1]));
}

// ---------------- scratch (device globals) ---------------------------------
__device__ float g_ts[(size_t)ROWS * TS_];
__device__ float g_add[(size_t)ROWS * 4096];
__device__ float g_qb[(size_t)ROWS * H_];
__device__ float g_kb[(size_t)ROWS * H_];
__device__ float g_vb[(size_t)ROWS * H_];
__device__ float g_Q[(size_t)ROWS * H_];
__device__ float g_K[(size_t)ROWS * H_];
__device__ float g_V[(size_t)ROWS * H_];
__device__ float g_attn[(size_t)ROWS * H_];

// bf16 split planes
__device__ __nv_bfloat16 g_Ahi[(size_t)ROWS * H_];
__device__ __nv_bfloat16 g_Alo[(size_t)ROWS * H_];
__device__ __nv_bfloat16 g_tsHi[(size_t)ROWS * TS_];
__device__ __nv_bfloat16 g_tsLo[(size_t)ROWS * TS_];
#define WOFF_Q  ((size_t)0)
#define WOFF_K  ((size_t)4194304)
#define WOFF_V  ((size_t)8388608)
#define WOFF_O  ((size_t)12582912)
#define WOFF_TS ((size_t)16777216)
#define WOFF_OR ((size_t)17825792)
#define WTOTAL  ((size_t)19922944)
__device__ __nv_bfloat16 g_WHi[WTOTAL];
__device__ __nv_bfloat16 g_WLo[WTOTAL];

// ---------------- convert kernels ------------------------------------------
__global__ void convertA_kernel(const float* __restrict__ src,
                                __nv_bfloat16* __restrict__ hi,
                                __nv_bfloat16* __restrict__ lo, int n4)
{
    int i = blockIdx.x * blockDim.x + threadIdx.x;
    if (i >= n4) return;
    float4 v = ((const float4*)src)[i];
    __nv_bfloat16 h0 = __float2bfloat16(v.x);
    __nv_bfloat16 h1 = __float2bfloat16(v.y);
    __nv_bfloat16 h2 = __float2bfloat16(v.z);
    __nv_bfloat16 h3 = __float2bfloat16(v.w);
    __nv_bfloat16 l0 = __float2bfloat16(v.x - __bfloat162float(h0));
    __nv_bfloat16 l1 = __float2bfloat16(v.y - __bfloat162float(h1));
    __nv_bfloat16 l2 = __float2bfloat16(v.z - __bfloat162float(h2));
    __nv_bfloat16 l3 = __float2bfloat16(v.w - __bfloat162float(h3));
    ushort4 hv = make_ushort4(__bfloat16_as_ushort(h0), __bfloat16_as_ushort(h1),
                              __bfloat16_as_ushort(h2), __bfloat16_as_ushort(h3));
    ushort4 lv = make_ushort4(__bfloat16_as_ushort(l0), __bfloat16_as_ushort(l1),
                              __bfloat16_as_ushort(l2), __bfloat16_as_ushort(l3));
    ((ushort4*)hi)[i] = hv;
    ((ushort4*)lo)[i] = lv;
}

// src [K][ld] fp32 -> dst [N][K] bf16 hi/lo (tiles 32x32, grid (K/32, N/32))
__global__ void convertBT_kernel(const float* __restrict__ src, int ld, int Kdim,
                                 __nv_bfloat16* __restrict__ hi,
                                 __nv_bfloat16* __restrict__ lo)
{
    __shared__ float t[32][33];
    int tx = threadIdx.x, ty = threadIdx.y;
    int k0 = blockIdx.x * 32, n0 = blockIdx.y * 32;
    #pragma unroll
    for (int i = 0; i < 4; i++)
        t[ty + 8 * i][tx] = src[(size_t)(k0 + ty + 8 * i) * ld + n0 + tx];
    __syncthreads();
    #pragma unroll
    for (int i = 0; i < 4; i++) {
        float v = t[tx][ty + 8 * i];
        __nv_bfloat16 h = __float2bfloat16(v);
        __nv_bfloat16 l = __float2bfloat16(v - __bfloat162float(h));
        size_t o = (size_t)(n0 + ty + 8 * i) * Kdim + k0 + tx;
        hi[o] = h; lo[o] = l;
    }
}

// ---------------- HMMA GEMM: C[M,N] = A @ B^T (+Add) -----------------------
// A planes [M][K], B planes [N][K] (bf16, K-major). 128x128 tile, BK=32,
// 8 warps (2x4), warp tile 64x32, 2-term split => 3 mma combos.
#define LDT    40                    // padded bf16 row stride (80 bytes)
#define PLSZ   (128*LDT*2)           // 10240 B per plane tile
#define BUFSZ  (4*PLSZ)              // AHi|ALo|BHi|BLo = 40960 B
#define GEMM_SMEM (2*BUFSZ)          // 81920 B double-buffered

__global__ __launch_bounds__(256) void gemm_mma(
    const __nv_bfloat16* __restrict__ Ahi, const __nv_bfloat16* __restrict__ Alo,
    const __nv_bfloat16* __restrict__ Bhi, const __nv_bfloat16* __restrict__ Blo,
    const float* __restrict__ Add, float* __restrict__ C,
    int K, int N, int ldadd)
{
    extern __shared__ char smc[];
    uint32_t sb = smem_u32(smc);
    int tid = threadIdx.x, lane = tid & 31, wid = tid >> 5;
    int wm = wid >> 2, wn = wid & 3;
    int tile_n = blockIdx.x * 128, tile_m = blockIdx.y * 128;

    // loader mapping: 2 planes x 128 rows; each thread owns one row (64B)
    int lrow = tid & 127, plane = tid >> 7;
    const uint4* Ag = (const uint4*)((plane ? Alo : Ahi) + (size_t)(tile_m + lrow) * K);
    const uint4* Bg = (const uint4*)((plane ? Blo : Bhi) + (size_t)(tile_n + lrow) * K);
    char* stA = smc + plane * PLSZ + lrow * (LDT * 2);
    char* stB = stA + 2 * PLSZ;

    float acc[4][4][4];
    #pragma unroll
    for (int i = 0; i < 4; i++)
        #pragma unroll
        for (int j = 0; j < 4; j++)
            #pragma unroll
            for (int e = 0; e < 4; e++) acc[i][j][e] = 0.f;

    int nch = K >> 5;

    // prologue: chunk 0
    uint4 va[4], vb[4];
    #pragma unroll
    for (int j = 0; j < 4; j++) { va[j] = Ag[j]; vb[j] = Bg[j]; }
    #pragma unroll
    for (int j = 0; j < 4; j++) {
        *(uint4*)(stA + j * 16) = va[j];
        *(uint4*)(stB + j * 16) = vb[j];
    }
    __syncthreads();

    for (int c = 0; c < nch; c++) {
        int buf = c & 1;
        if (c + 1 < nch) {
            int kq = (c + 1) * 4;
            #pragma unroll
            for (int j = 0; j < 4; j++) { va[j] = Ag[kq + j]; vb[j] = Bg[kq + j]; }
        }

        // compute on buf
        uint32_t base = sb + buf * BUFSZ;
        #pragma unroll
        for (int s = 0; s < 2; s++) {
            uint32_t bh[4][2], bl[4][2];
            #pragma unroll
            for (int j = 0; j < 4; j++) {
                uint32_t r = (uint32_t)(wn * 32 + j * 8 + (lane & 7)) * 80
                           + s * 32 + ((lane >> 3) & 1) * 16;
                ldsm2(bh[j], base + 2 * PLSZ + r);
                ldsm2(bl[j], base + 3 * PLSZ + r);
            }
            #pragma unroll
            for (int i = 0; i < 4; i++) {
                uint32_t ra = (uint32_t)(wm * 64 + i * 16 + (lane & 7) + ((lane >> 3) & 1) * 8) * 80
                            + s * 32 + ((lane >> 4) & 1) * 16;
                uint32_t ah[4], al[4];
                ldsm4(ah, base + ra);
                ldsm4(al, base + PLSZ + ra);
                #pragma unroll
                for (int j = 0; j < 4; j++) {
                    mma16816(acc[i][j], ah, bh[j]);
                    mma16816(acc[i][j], al, bh[j]);
                    mma16816(acc[i][j], ah, bl[j]);
                }
            }
        }

        if (c + 1 < nch) {
            char* dA = smc + (buf ^ 1) * BUFSZ + plane * PLSZ + lrow * (LDT * 2);
            char* dB = dA + 2 * PLSZ;
            #pragma unroll
            for (int j = 0; j < 4; j++) {
                *(uint4*)(dA + j * 16) = va[j];
                *(uint4*)(dB + j * 16) = vb[j];
            }
            __syncthreads();
        }
    }

    // epilogue
    #pragma unroll
    for (int i = 0; i < 4; i++) {
        int row = tile_m + wm * 64 + i * 16 + (lane >> 2);
        #pragma unroll
        for (int j = 0; j < 4; j++) {
            int col = tile_n + wn * 32 + j * 8 + (lane & 3) * 2;
            float2 v0 = make_float2(acc[i][j][0], acc[i][j][1]);
            float2 v1 = make_float2(acc[i][j][2], acc[i][j][3]);
            if (Add) {
                float2 a0 = *(const float2*)&Add[(size_t)row * ldadd + col];
                float2 a1 = *(const float2*)&Add[(size_t)(row + 8) * ldadd + col];
                v0.x += a0.x; v0.y += a0.y;
                v1.x += a1.x; v1.y += a1.y;
            }
            *(float2*)&C[(size_t)row * N + col] = v0;
            *(float2*)&C[(size_t)(row + 8) * N + col] = v1;
        }
    }
}

// -------- blend + rmsnorm + exact k-th order statistic + relu-shift --------
__global__ __launch_bounds__(512) void ts_rowops_kernel(
    const float* __restrict__ last, const float* __restrict__ w, float* __restrict__ ts)
{
    __shared__ float sv[512];
    __shared__ float rbuf[512];
    int row = blockIdx.x;
    int j = threadIdx.x;
    size_t idx = (size_t)row * TS_ + j;

    float x = 0.5f * ts[idx] + 0.5f * last[idx];
    rbuf[j] = x * x;
    __syncthreads();
    #pragma unroll
    for (int s2 = 256; s2 > 0; s2 >>= 1) {
        if (j < s2) rbuf[j] += rbuf[j + s2];
        __syncthreads();
    }
    float var = rbuf[0] * (1.f / 512.f);
    float y = x * rsqrtf(var + 1e-6f) * w[j];
    sv[j] = y;
    __syncthreads();

    for (int k = 2; k <= 512; k <<= 1) {
        for (int jj = k >> 1; jj > 0; jj >>= 1) {
            int ixj = j ^ jj;
            if (ixj > j) {
                float a = sv[j], b = sv[ixj];
                bool asc = ((j & k) == 0);
                if (asc ? (a > b) : (a < b)) { sv[j] = b; sv[ixj] = a; }
            }
            __syncthreads();
        }
    }
    float kth = sv[KIDX - 1];
    ts[idx] = fmaxf(y - kth, 0.f);
}

// ---------------- RoPE + transpose to head-major [B,NH,S,HD] --------------
__global__ void rope_transpose_kernel(
    const float* __restrict__ qb, const float* __restrict__ kb, const float* __restrict__ vb,
    float* __restrict__ Q, float* __restrict__ Ko, float* __restrict__ V)
{
    int i = blockIdx.x * blockDim.x + threadIdx.x;
    if (i >= ROWS * NH_ * 64) return;
    int d = i & 63;
    int h = (i >> 6) & (NH_ - 1);
    int row = i >> 10;
    int b = row >> 11;
    int s = row & (S_ - 1);

    float inv = (float)exp(-(double)d * (9.210340371976184 / 64.0));
    float ang = (float)s * inv;
    float cs, sn;
    sincosf(ang, &sn, &cs);

    size_t src = (size_t)row * H_ + h * HD_ + d;
    float q0 = qb[src], q1 = qb[src + 64];
    float k0 = kb[src], k1 = kb[src + 64];
    size_t dst = ((size_t)(b * NH_ + h) * S_ + s) * HD_ + d;
    Q[dst]       = q0 * cs - q1 * sn;
    Q[dst + 64]  = q1 * cs + q0 * sn;
    Ko[dst]      = k0 * cs - k1 * sn;
    Ko[dst + 64] = k1 * cs + k0 * sn;
    V[dst]       = vb[src];
    V[dst + 64]  = vb[src + 64];
}

// ---------------- flash attention (fp32, causal, online softmax) ----------
#define FBM 64
#define FBN 64
#define PS_LD 68
#define FLASH_SMEM ((FBM*HD_ + FBN*HD_ + FBN*HD_ + FBM*PS_LD) * 4)

__global__ __launch_bounds__(256) void flash_kernel(
    const float* __restrict__ Qg, const float* __restrict__ Kg,
    const float* __restrict__ Vg, float* __restrict__ Og)
{
    extern __shared__ float sm[];
    float* Qs = sm;
    float* Ks = Qs + FBM * HD_;
    float* Vs = Ks + FBN * HD_;
    float* Ps = Vs + FBN * HD_;

    int qt = blockIdx.x;
    int bh = blockIdx.y;
    int tid = threadIdx.x;

    const float* Qbase = Qg + ((size_t)bh * S_ + (size_t)qt * FBM) * HD_;
    const float* Kbase = Kg + (size_t)bh * S_ * HD_;
    const float* Vbase = Vg + (size_t)bh * S_ * HD_;

    for (int i = tid; i < FBM * HD_ / 4; i += 256)
        ((float4*)Qs)[i] = ((const float4*)Qbase)[i];

    int ty = tid >> 4, tx = tid & 15;
    int r0 = ty * 4, c0 = tx * 4;

    float m_i[4], l_i[4];
    u64 acc2[4][4];
    #pragma unroll
    for (int i = 0; i < 4; i++) {
        m_i[i] = -INFINITY; l_i[i] = 0.f;
        #pragma unroll
        for (int j = 0; j < 4; j++) acc2[i][j] = 0ull;
    }
    const float scale = 0.08838834764831845f;

    for (int kt = 0; kt <= qt; ++kt) {
        __syncthreads();
        const float4* Ksrc = (const float4*)(Kbase + (size_t)kt * FBN * HD_);
        const float4* Vsrc = (const float4*)(Vbase + (size_t)kt * FBN * HD_);
        for (int i = tid; i < FBN * HD_ / 4; i += 256) {
            ((float4*)Ks)[i] = Ksrc[i];
            ((float4*)Vs)[i] = Vsrc[i];
        }
        __syncthreads();

        u64 s2[4][4];
        #pragma unroll
        for (int i = 0; i < 4; i++)
            #pragma unroll
            for (int j = 0; j < 4; j++) s2[i][j] = 0ull;

        for (int d0 = 0; d0 < HD_; d0 += 4) {
            ulonglong2 qv[4], kv[4];
            #pragma unroll
            for (int i = 0; i < 4; i++) qv[i] = *(const ulonglong2*)&Qs[(r0 + i) * HD_ + d0];
            #pragma unroll
            for (int j = 0; j < 4; j++) kv[j] = *(const ulonglong2*)&Ks[(c0 + j) * HD_ + d0];
            #pragma unroll
            for (int i = 0; i < 4; i++)
                #pragma unroll
                for (int j = 0; j < 4; j++) {
                    s2[i][j] = fma2(qv[i].x, kv[j].x, s2[i][j]);
                    s2[i][j] = fma2(qv[i].y, kv[j].y, s2[i][j]);
                }
        }

        float s[4][4];
        #pragma unroll
        for (int i = 0; i < 4; i++)
            #pragma unroll
            for (int j = 0; j < 4; j++) {
                float lo, hi; unpack2(s2[i][j], lo, hi);
                s[i][j] = lo + hi;
            }

        if (kt == qt) {
            #pragma unroll
            for (int i = 0; i < 4; i++)
                #pragma unroll
                for (int j = 0; j < 4; j++)
                    s[i][j] = (c0 + j <= r0 + i) ? s[i][j] * scale : -1e30f;
        } else {
            #pragma unroll
            for (int i = 0; i < 4; i++)
                #pragma unroll
                for (int j = 0; j < 4; j++) s[i][j] *= scale;
        }

        #pragma unroll
        for (int i = 0; i < 4; i++) {
            float rm = fmaxf(fmaxf(s[i][0], s[i][1]), fmaxf(s[i][2], s[i][3]));
            #pragma unroll
            for (int off = 8; off >= 1; off >>= 1)
                rm = fmaxf(rm, __shfl_xor_sync(0xffffffffu, rm, off));
            float mnew = fmaxf(m_i[i], rm);
            float corr = __expf(m_i[i] - mnew);
            float rs = 0.f;
            #pragma unroll
            for (int j = 0; j < 4; j++) {
                float p = __expf(s[i][j] - mnew);
                Ps[(r0 + i) * PS_LD + c0 + j] = p;
                rs += p;
            }
            #pragma unroll
            for (int off = 8; off >= 1; off >>= 1)
                rs += __shfl_xor_sync(0xffffffffu, rs, off);
            l_i[i] = l_i[i] * corr + rs;
            m_i[i] = mnew;
            u64 cd = dup2(corr);
            #pragma unroll
            for (int j = 0; j < 4; j++) acc2[i][j] = mul2(acc2[i][j], cd);
        }
        __syncthreads();

        int vc = tx * 8;
        #pragma unroll 4
        for (int k = 0; k < FBN; k++) {
            ulonglong2 v0 = *(const ulonglong2*)&Vs[k * HD_ + vc];
            ulonglong2 v1 = *(const ulonglong2*)&Vs[k * HD_ + vc + 4];
            u64 vv0 = v0.x, vv1 = v0.y, vv2 = v1.x, vv3 = v1.y;
            #pragma unroll
            for (int i = 0; i < 4; i++) {
                u64 pd = dup2(Ps[(r0 + i) * PS_LD + k]);
                acc2[i][0] = fma2(pd, vv0, acc2[i][0]);
                acc2[i][1] = fma2(pd, vv1, acc2[i][1]);
                acc2[i][2] = fma2(pd, vv2, acc2[i][2]);
                acc2[i][3] = fma2(pd, vv3, acc2[i][3]);
            }
        }
    }

    int b = bh >> 4, h = bh & (NH_ - 1);
    #pragma unroll
    for (int i = 0; i < 4; i++) {
        u64 rl = dup2(1.f / l_i[i]);
        int srow = qt * FBM + r0 + i;
        float* dst = Og + ((size_t)(b * S_ + srow)) * H_ + h * HD_ + tx * 8;
        ulonglong2 st0, st1;
        st0.x = mul2(acc2[i][0], rl); st0.y = mul2(acc2[i][1], rl);
        st1.x = mul2(acc2[i][2], rl); st1.y = mul2(acc2[i][3], rl);
        ((ulonglong2*)dst)[0] = st0;
        ((ulonglong2*)dst)[1] = st1;
    }
}

// ---------------------------------------------------------------------------
extern "C" void kernel_launch(void* const* d_in, const int* in_sizes, int n_in,
                              void* d_out, int out_size)
{
    const float* hidden = (const float*)d_in[0];
    const float* lastts = (const float*)d_in[1];
    const float* Wq     = (const float*)d_in[2];
    const float* Wk     = (const float*)d_in[3];
    const float* Wv     = (const float*)d_in[4];
    const float* Wo     = (const float*)d_in[5];
    const float* Wts    = (const float*)d_in[6];
    const float* tsw    = (const float*)d_in[7];
    const float* Worig  = (const float*)d_in[8];
    float* out = (float*)d_out;

    float *ts, *add, *qb, *kb, *vb, *Q, *K, *V, *attn;
    __nv_bfloat16 *Ahi, *Alo, *tsHi, *tsLo, *WHi, *WLo;
    cudaGetSymbolAddress((void**)&ts,   g_ts);
    cudaGetSymbolAddress((void**)&add,  g_add);
    cudaGetSymbolAddress((void**)&qb,   g_qb);
    cudaGetSymbolAddress((void**)&kb,   g_kb);
    cudaGetSymbolAddress((void**)&vb,   g_vb);
    cudaGetSymbolAddress((void**)&Q,    g_Q);
    cudaGetSymbolAddress((void**)&K,    g_K);
    cudaGetSymbolAddress((void**)&V,    g_V);
    cudaGetSymbolAddress((void**)&attn, g_attn);
    cudaGetSymbolAddress((void**)&Ahi,  g_Ahi);
    cudaGetSymbolAddress((void**)&Alo,  g_Alo);
    cudaGetSymbolAddress((void**)&tsHi, g_tsHi);
    cudaGetSymbolAddress((void**)&tsLo, g_tsLo);
    cudaGetSymbolAddress((void**)&WHi,  g_WHi);
    cudaGetSymbolAddress((void**)&WLo,  g_WLo);

    cudaFuncSetAttribute(gemm_mma, cudaFuncAttributeMaxDynamicSharedMemorySize, GEMM_SMEM);
    cudaFuncSetAttribute(flash_kernel, cudaFuncAttributeMaxDynamicSharedMemorySize, FLASH_SMEM);

    // 0) converts: weights (transposed) + hidden
    dim3 tb(32, 8);
    convertBT_kernel<<<dim3(64, 64), tb>>>(Wq, 2048, 2048, WHi + WOFF_Q, WLo + WOFF_Q);
    convertBT_kernel<<<dim3(64, 64), tb>>>(Wk, 2048, 2048, WHi + WOFF_K, WLo + WOFF_K);
    convertBT_kernel<<<dim3(64, 64), tb>>>(Wv, 2048, 2048, WHi + WOFF_V, WLo + WOFF_V);
    convertBT_kernel<<<dim3(64, 64), tb>>>(Wo, 2048, 2048, WHi + WOFF_O, WLo + WOFF_O);
    convertBT_kernel<<<dim3(64, 16), tb>>>(Wts, 512, 2048, WHi + WOFF_TS, WLo + WOFF_TS);
    convertBT_kernel<<<dim3(16, 128), tb>>>(Worig, 6144, 512, WHi + WOFF_OR, WLo + WOFF_OR);
    convertA_kernel<<<(ROWS * H_ / 4 + 255) / 256, 256>>>(hidden, Ahi, Alo, ROWS * H_ / 4);

    // 1) ts = hidden @ Wts
    gemm_mma<<<dim3(4, 32), 256, GEMM_SMEM>>>(Ahi, Alo, WHi + WOFF_TS, WLo + WOFF_TS,
                                              nullptr, ts, 2048, 512, 0);
    // 2) blend + rmsnorm + kth + relu
    ts_rowops_kernel<<<ROWS, 512>>>(lastts, tsw, ts);
    // 3) convert ts, then add = ts @ Worig[:, :4096]
    convertA_kernel<<<(ROWS * TS_ / 4 + 255) / 256, 256>>>(ts, tsHi, tsLo, ROWS * TS_ / 4);
    gemm_mma<<<dim3(32, 32), 256, GEMM_SMEM>>>(tsHi, tsLo, WHi + WOFF_OR, WLo + WOFF_OR,
                                               nullptr, add, 512, 4096, 0);
    // 4) q/k/v
    gemm_mma<<<dim3(16, 32), 256, GEMM_SMEM>>>(Ahi, Alo, WHi + WOFF_Q, WLo + WOFF_Q,
                                               add,        qb, 2048, 2048, 4096);
    gemm_mma<<<dim3(16, 32), 256, GEMM_SMEM>>>(Ahi, Alo, WHi + WOFF_K, WLo + WOFF_K,
                                               add + 2048, kb, 2048, 2048, 4096);
    gemm_mma<<<dim3(16, 32), 256, GEMM_SMEM>>>(Ahi, Alo, WHi + WOFF_V, WLo + WOFF_V,
                                               add + 2048, vb, 2048, 2048, 4096);
    // 5) RoPE + transpose
    int tot = ROWS * NH_ * 64;
    rope_transpose_kernel<<<(tot + 255) / 256, 256>>>(qb, kb, vb, Q, K, V);
    // 6) causal flash attention
    flash_kernel<<<dim3(S_/FBM, B_*NH_), 256, FLASH_SMEM>>>(Q, K, V, attn);
    // 7) out = attn @ Wo
    convertA_kernel<<<(ROWS * H_ / 4 + 255) / 256, 256>>>(attn, Ahi, Alo, ROWS * H_ / 4);
    gemm_mma<<<dim3(16, 32), 256, GEMM_SMEM>>>(Ahi, Alo, WHi + WOFF_O, WLo + WOFF_O,
                                               nullptr, out, 2048, 2048, 0);
}

// round 6
// speedup vs baseline: 1.8660x; 1.4526x over previous
#include <cuda_runtime.h>
#include <cuda_bf16.h>
#include <math.h>
#include <stdint.h>

#define B_   2
#define S_   2048
#define H_   2048
#define NH_  16
#define HD_  128
#define TS_  512
#define ROWS (B_*S_)        // 4096
#define KIDX 460

typedef unsigned long long u64;

// ------------------------- mma.sync helpers (baseline PTX) -----------------
__device__ __forceinline__ uint32_t smem_u32(const void* p) {
    uint32_t a;
    asm("{ .reg .u64 t; cvta.to.shared.u64 t,%1; cvt.u32.u64 %0,t; }" : "=r"(a) : "l"(p));
    return a;
}
__device__ __forceinline__ void ldsm4(uint32_t* r, uint32_t addr) {
    asm volatile("ldmatrix.sync.aligned.m8n8.x4.shared.b16 {%0,%1,%2,%3},[%4];"
        : "=r"(r[0]), "=r"(r[1]), "=r"(r[2]), "=r"(r[3]) : "r"(addr));
}
__device__ __forceinline__ void ldsm4t(uint32_t* r, uint32_t addr) {
    asm volatile("ldmatrix.sync.aligned.m8n8.x4.trans.shared.b16 {%0,%1,%2,%3},[%4];"
        : "=r"(r[0]), "=r"(r[1]), "=r"(r[2]), "=r"(r[3]) : "r"(addr));
}
__device__ __forceinline__ void ldsm2(uint32_t* r, uint32_t addr) {
    asm volatile("ldmatrix.sync.aligned.m8n8.x2.shared.b16 {%0,%1},[%2];"
        : "=r"(r[0]), "=r"(r[1]) : "r"(addr));
}
__device__ __forceinline__ void mma16816(float* c, const uint32_t* a, const uint32_t* b) {
    asm volatile(
        "mma.sync.aligned.m16n8k16.row.col.f32.bf16.bf16.f32 "
        "{%0,%1,%2,%3},{%4,%5,%6,%7},{%8,%9},{%0,%1,%2,%3};"
        : "+f"(c[0]), "+f"(c[1]), "+f"(c[2]), "+f"(c[3])
        : "r"(a[0]), "r"(a[1]), "r"(a[2]), "r"(a[3]), "r"(b[0]), "r"(b[1]));
}
__device__ __forceinline__ uint32_t pack_bf16(float a, float b) {
    __nv_bfloat16 ha = __float2bfloat16_rn(a), hb = __float2bfloat16_rn(b);
    return (uint32_t)__bfloat16_as_ushort(ha) | ((uint32_t)__bfloat16_as_ushort(hb) << 16);
}
__device__ __forceinline__ void split_store(float v, __nv_bfloat16* hi, __nv_bfloat16* lo, size_t idx) {
    __nv_bfloat16 h = __float2bfloat16_rn(v);
    hi[idx] = h;
    lo[idx] = __float2bfloat16_rn(v - __bfloat162float(h));
}

// ---------------- scratch (device globals) ---------------------------------
__device__ float g_ts[(size_t)ROWS * TS_];
__device__ float g_add[(size_t)ROWS * 4096];
__device__ float g_qb[(size_t)ROWS * H_];
__device__ float g_kb[(size_t)ROWS * H_];
__device__ float g_vb[(size_t)ROWS * H_];

// bf16 split planes
__device__ __nv_bfloat16 g_Ahi[(size_t)ROWS * H_];   // hidden, later attn-out
__device__ __nv_bfloat16 g_Alo[(size_t)ROWS * H_];
__device__ __nv_bfloat16 g_tsHi[(size_t)ROWS * TS_];
__device__ __nv_bfloat16 g_tsLo[(size_t)ROWS * TS_];
// head-major [B,NH,S,HD] bf16 planes for attention
__device__ __nv_bfloat16 g_Qhi[(size_t)ROWS * H_];
__device__ __nv_bfloat16 g_Qlo[(size_t)ROWS * H_];
__device__ __nv_bfloat16 g_Khi[(size_t)ROWS * H_];
__device__ __nv_bfloat16 g_Klo[(size_t)ROWS * H_];
__device__ __nv_bfloat16 g_Vhi[(size_t)ROWS * H_];
__device__ __nv_bfloat16 g_Vlo[(size_t)ROWS * H_];

#define WOFF_Q  ((size_t)0)
#define WOFF_K  ((size_t)4194304)
#define WOFF_V  ((size_t)8388608)
#define WOFF_O  ((size_t)12582912)
#define WOFF_TS ((size_t)16777216)
#define WOFF_OR ((size_t)17825792)
#define WTOTAL  ((size_t)19922944)
__device__ __nv_bfloat16 g_WHi[WTOTAL];
__device__ __nv_bfloat16 g_WLo[WTOTAL];

// ---------------- convert kernels ------------------------------------------
__global__ void convertA_kernel(const float* __restrict__ src,
                                __nv_bfloat16* __restrict__ hi,
                                __nv_bfloat16* __restrict__ lo, int n4)
{
    int i = blockIdx.x * blockDim.x + threadIdx.x;
    if (i >= n4) return;
    float4 v = ((const float4*)src)[i];
    __nv_bfloat16 h0 = __float2bfloat16(v.x);
    __nv_bfloat16 h1 = __float2bfloat16(v.y);
    __nv_bfloat16 h2 = __float2bfloat16(v.z);
    __nv_bfloat16 h3 = __float2bfloat16(v.w);
    __nv_bfloat16 l0 = __float2bfloat16(v.x - __bfloat162float(h0));
    __nv_bfloat16 l1 = __float2bfloat16(v.y - __bfloat162float(h1));
    __nv_bfloat16 l2 = __float2bfloat16(v.z - __bfloat162float(h2));
    __nv_bfloat16 l3 = __float2bfloat16(v.w - __bfloat162float(h3));
    ushort4 hv = make_ushort4(__bfloat16_as_ushort(h0), __bfloat16_as_ushort(h1),
                              __bfloat16_as_ushort(h2), __bfloat16_as_ushort(h3));
    ushort4 lv = make_ushort4(__bfloat16_as_ushort(l0), __bfloat16_as_ushort(l1),
                              __bfloat16_as_ushort(l2), __bfloat16_as_ushort(l3));
    ((ushort4*)hi)[i] = hv;
    ((ushort4*)lo)[i] = lv;
}

// src [K][ld] fp32 -> dst [N][K] bf16 hi/lo (tiles 32x32, grid (K/32, N/32))
__global__ void convertBT_kernel(const float* __restrict__ src, int ld, int Kdim,
                                 __nv_bfloat16* __restrict__ hi,
                                 __nv_bfloat16* __restrict__ lo)
{
    __shared__ float t[32][33];
    int tx = threadIdx.x, ty = threadIdx.y;
    int k0 = blockIdx.x * 32, n0 = blockIdx.y * 32;
    #pragma unroll
    for (int i = 0; i < 4; i++)
        t[ty + 8 * i][tx] = src[(size_t)(k0 + ty + 8 * i) * ld + n0 + tx];
    __syncthreads();
    #pragma unroll
    for (int i = 0; i < 4; i++) {
        float v = t[tx][ty + 8 * i];
        __nv_bfloat16 h = __float2bfloat16(v);
        __nv_bfloat16 l = __float2bfloat16(v - __bfloat162float(h));
        size_t o = (size_t)(n0 + ty + 8 * i) * Kdim + k0 + tx;
        hi[o] = h; lo[o] = l;
    }
}

// ---------------- HMMA GEMM: C[M,N] = A @ B^T (+Add) -----------------------
#define LDT    40
#define PLSZ   (128*LDT*2)
#define BUFSZ  (4*PLSZ)
#define GEMM_SMEM (2*BUFSZ)

__global__ __launch_bounds__(256) void gemm_mma(
    const __nv_bfloat16* __restrict__ Ahi, const __nv_bfloat16* __restrict__ Alo,
    const __nv_bfloat16* __restrict__ Bhi, const __nv_bfloat16* __restrict__ Blo,
    const float* __restrict__ Add, float* __restrict__ C,
    int K, int N, int ldadd)
{
    extern __shared__ char smc[];
    uint32_t sb = smem_u32(smc);
    int tid = threadIdx.x, lane = tid & 31, wid = tid >> 5;
    int wm = wid >> 2, wn = wid & 3;
    int tile_n = blockIdx.x * 128, tile_m = blockIdx.y * 128;

    int lrow = tid & 127, plane = tid >> 7;
    const uint4* Ag = (const uint4*)((plane ? Alo : Ahi) + (size_t)(tile_m + lrow) * K);
    const uint4* Bg = (const uint4*)((plane ? Blo : Bhi) + (size_t)(tile_n + lrow) * K);
    char* stA = smc + plane * PLSZ + lrow * (LDT * 2);
    char* stB = stA + 2 * PLSZ;

    float acc[4][4][4];
    #pragma unroll
    for (int i = 0; i < 4; i++)
        #pragma unroll
        for (int j = 0; j < 4; j++)
            #pragma unroll
            for (int e = 0; e < 4; e++) acc[i][j][e] = 0.f;

    int nch = K >> 5;
    uint4 va[4], vb[4];
    #pragma unroll
    for (int j = 0; j < 4; j++) { va[j] = Ag[j]; vb[j] = Bg[j]; }
    #pragma unroll
    for (int j = 0; j < 4; j++) {
        *(uint4*)(stA + j * 16) = va[j];
        *(uint4*)(stB + j * 16) = vb[j];
    }
    __syncthreads();

    for (int c = 0; c < nch; c++) {
        int buf = c & 1;
        if (c + 1 < nch) {
            int kq = (c + 1) * 4;
            #pragma unroll
            for (int j = 0; j < 4; j++) { va[j] = Ag[kq + j]; vb[j] = Bg[kq + j]; }
        }
        uint32_t base = sb + buf * BUFSZ;
        #pragma unroll
        for (int s = 0; s < 2; s++) {
            uint32_t bh[4][2], bl[4][2];
            #pragma unroll
            for (int j = 0; j < 4; j++) {
                uint32_t r = (uint32_t)(wn * 32 + j * 8 + (lane & 7)) * 80
                           + s * 32 + ((lane >> 3) & 1) * 16;
                ldsm2(bh[j], base + 2 * PLSZ + r);
                ldsm2(bl[j], base + 3 * PLSZ + r);
            }
            #pragma unroll
            for (int i = 0; i < 4; i++) {
                uint32_t ra = (uint32_t)(wm * 64 + i * 16 + (lane & 7) + ((lane >> 3) & 1) * 8) * 80
                            + s * 32 + ((lane >> 4) & 1) * 16;
                uint32_t ah[4], al[4];
                ldsm4(ah, base + ra);
                ldsm4(al, base + PLSZ + ra);
                #pragma unroll
                for (int j = 0; j < 4; j++) {
                    mma16816(acc[i][j], ah, bh[j]);
                    mma16816(acc[i][j], al, bh[j]);
                    mma16816(acc[i][j], ah, bl[j]);
                }
            }
        }
        if (c + 1 < nch) {
            char* dA = smc + (buf ^ 1) * BUFSZ + plane * PLSZ + lrow * (LDT * 2);
            char* dB = dA + 2 * PLSZ;
            #pragma unroll
            for (int j = 0; j < 4; j++) {
                *(uint4*)(dA + j * 16) = va[j];
                *(uint4*)(dB + j * 16) = vb[j];
            }
            __syncthreads();
        }
    }

    #pragma unroll
    for (int i = 0; i < 4; i++) {
        int row = tile_m + wm * 64 + i * 16 + (lane >> 2);
        #pragma unroll
        for (int j = 0; j < 4; j++) {
            int col = tile_n + wn * 32 + j * 8 + (lane & 3) * 2;
            float2 v0 = make_float2(acc[i][j][0], acc[i][j][1]);
            float2 v1 = make_float2(acc[i][j][2], acc[i][j][3]);
            if (Add) {
                float2 a0 = *(const float2*)&Add[(size_t)row * ldadd + col];
                float2 a1 = *(const float2*)&Add[(size_t)(row + 8) * ldadd + col];
                v0.x += a0.x; v0.y += a0.y;
                v1.x += a1.x; v1.y += a1.y;
            }
            *(float2*)&C[(size_t)row * N + col] = v0;
            *(float2*)&C[(size_t)(row + 8) * N + col] = v1;
        }
    }
}

// -------- blend + rmsnorm + exact k-th + relu-shift; writes bf16 planes ----
__global__ __launch_bounds__(512) void ts_rowops_kernel(
    const float* __restrict__ last, const float* __restrict__ w,
    const float* __restrict__ ts,
    __nv_bfloat16* __restrict__ tsHi, __nv_bfloat16* __restrict__ tsLo)
{
    __shared__ float sv[512];
    __shared__ float rbuf[512];
    int row = blockIdx.x;
    int j = threadIdx.x;
    size_t idx = (size_t)row * TS_ + j;

    float x = 0.5f * ts[idx] + 0.5f * last[idx];
    rbuf[j] = x * x;
    __syncthreads();
    #pragma unroll
    for (int s2 = 256; s2 > 0; s2 >>= 1) {
        if (j < s2) rbuf[j] += rbuf[j + s2];
        __syncthreads();
    }
    float var = rbuf[0] * (1.f / 512.f);
    float y = x * rsqrtf(var + 1e-6f) * w[j];
    sv[j] = y;
    __syncthreads();

    for (int k = 2; k <= 512; k <<= 1) {
        for (int jj = k >> 1; jj > 0; jj >>= 1) {
            int ixj = j ^ jj;
            if (ixj > j) {
                float a = sv[j], b = sv[ixj];
                bool asc = ((j & k) == 0);
                if (asc ? (a > b) : (a < b)) { sv[j] = b; sv[ixj] = a; }
            }
            __syncthreads();
        }
    }
    float kth = sv[KIDX - 1];
    split_store(fmaxf(y - kth, 0.f), tsHi, tsLo, idx);
}

// ------- RoPE + transpose to head-major bf16 hi/lo planes [B,NH,S,HD] ------
__global__ void rope_transpose_kernel(
    const float* __restrict__ qb, const float* __restrict__ kb, const float* __restrict__ vb,
    __nv_bfloat16* __restrict__ Qhi, __nv_bfloat16* __restrict__ Qlo,
    __nv_bfloat16* __restrict__ Khi, __nv_bfloat16* __restrict__ Klo,
    __nv_bfloat16* __restrict__ Vhi, __nv_bfloat16* __restrict__ Vlo)
{
    int i = blockIdx.x * blockDim.x + threadIdx.x;
    if (i >= ROWS * NH_ * 64) return;
    int d = i & 63;
    int h = (i >> 6) & (NH_ - 1);
    int row = i >> 10;
    int b = row >> 11;
    int s = row & (S_ - 1);

    float inv = (float)exp(-(double)d * (9.210340371976184 / 64.0));
    float ang = (float)s * inv;
    float cs, sn;
    sincosf(ang, &sn, &cs);

    size_t src = (size_t)row * H_ + h * HD_ + d;
    float q0 = qb[src], q1 = qb[src + 64];
    float k0 = kb[src], k1 = kb[src + 64];
    size_t dst = ((size_t)(b * NH_ + h) * S_ + s) * HD_ + d;
    split_store(q0 * cs - q1 * sn, Qhi, Qlo, dst);
    split_store(q1 * cs + q0 * sn, Qhi, Qlo, dst + 64);
    split_store(k0 * cs - k1 * sn, Khi, Klo, dst);
    split_store(k1 * cs + k0 * sn, Khi, Klo, dst + 64);
    split_store(vb[src],      Vhi, Vlo, dst);
    split_store(vb[src + 64], Vhi, Vlo, dst + 64);
}

// ---------------- flash attention on mma.sync (bf16 split) -----------------
// 64 q-rows/CTA, 64 keys/iter, 4 warps x 16 rows. Writes attn as bf16 planes.
#define LDB2  272                       // bytes per smem row (136 bf16)
#define TQH   0
#define TQL   17408
#define TKH   34816
#define TKL   52224
#define TVH   69632
#define TVL   87040
#define FLASH_SMEM2 104448

__global__ __launch_bounds__(128) void flash_mma(
    const __nv_bfloat16* __restrict__ Qhi, const __nv_bfloat16* __restrict__ Qlo,
    const __nv_bfloat16* __restrict__ Khi, const __nv_bfloat16* __restrict__ Klo,
    const __nv_bfloat16* __restrict__ Vhi, const __nv_bfloat16* __restrict__ Vlo,
    __nv_bfloat16* __restrict__ Ohi, __nv_bfloat16* __restrict__ Olo)
{
    extern __shared__ char sm[];
    uint32_t sb = smem_u32(sm);
    int tid = threadIdx.x, l = tid & 31, w = tid >> 5;
    int qt = blockIdx.x, bh = blockIdx.y;
    size_t bhS = (size_t)bh * S_;

    // load Q tile (2 planes x 64 rows x 16 uint4)
    for (int i = tid; i < 2048; i += 128) {
        int plane = i >> 10, rem = i & 1023, row = rem >> 4, c = rem & 15;
        const uint4* src = (const uint4*)((plane ? Qlo : Qhi) + (bhS + (size_t)qt * 64 + row) * HD_);
        *(uint4*)(sm + (plane ? TQL : TQH) + row * LDB2 + c * 16) = src[c];
    }

    float o[16][4];
    #pragma unroll
    for (int t = 0; t < 16; t++)
        #pragma unroll
        for (int e = 0; e < 4; e++) o[t][e] = 0.f;
    float m1 = -INFINITY, m2 = -INFINITY, l1 = 0.f, l2 = 0.f;
    const float scale = 0.08838834764831845f;

    for (int kt = 0; kt <= qt; kt++) {
        __syncthreads();
        for (int i = tid; i < 4096; i += 128) {
            int plane = i >> 10, rem = i & 1023, row = rem >> 4, c = rem & 15;
            const __nv_bfloat16* bp = (plane == 0) ? Khi : (plane == 1) ? Klo
                                      : (plane == 2) ? Vhi : Vlo;
            const uint4* src = (const uint4*)(bp + (bhS + (size_t)kt * 64 + row) * HD_);
            uint32_t off = (plane == 0) ? TKH : (plane == 1) ? TKL : (plane == 2) ? TVH : TVL;
            *(uint4*)(sm + off + row * LDB2 + c * 16) = src[c];
        }
        __syncthreads();

        // ---- S = Q K^T ----
        float s[8][4];
        #pragma unroll
        for (int t = 0; t < 8; t++)
            #pragma unroll
            for (int e = 0; e < 4; e++) s[t][e] = 0.f;

        #pragma unroll
        for (int kk = 0; kk < 8; kk++) {
            uint32_t ah[4], al[4];
            uint32_t ra = sb + TQH + (uint32_t)(w * 16 + (l & 15)) * LDB2
                        + ((l >> 4) & 1) * 16 + kk * 32;
            ldsm4(ah, ra);
            ldsm4(al, ra + (TQL - TQH));
            #pragma unroll
            for (int g = 0; g < 4; g++) {
                uint32_t bhv[4], blv[4];
                uint32_t rb = sb + TKH
                    + (uint32_t)(16 * g + (l & 7) + ((l >> 4) & 1) * 8) * LDB2
                    + ((l >> 3) & 1) * 16 + kk * 32;
                ldsm4(bhv, rb);
                ldsm4(blv, rb + (TKL - TKH));
                mma16816(s[2 * g],     ah, bhv);
                mma16816(s[2 * g],     al, bhv);
                mma16816(s[2 * g],     ah, blv);
                mma16816(s[2 * g + 1], ah, bhv + 2);
                mma16816(s[2 * g + 1], al, bhv + 2);
                mma16816(s[2 * g + 1], ah, blv + 2);
            }
        }

        // ---- scale + causal mask ----
        int r1 = (qt << 6) + w * 16 + (l >> 2), r2 = r1 + 8;
        int cb = (kt << 6) + ((l & 3) << 1);
        if (kt == qt) {
            #pragma unroll
            for (int t = 0; t < 8; t++) {
                int c0 = cb + t * 8, c1 = c0 + 1;
                s[t][0] = (c0 <= r1) ? s[t][0] * scale : -1e30f;
                s[t][1] = (c1 <= r1) ? s[t][1] * scale : -1e30f;
                s[t][2] = (c0 <= r2) ? s[t][2] * scale : -1e30f;
                s[t][3] = (c1 <= r2) ? s[t][3] * scale : -1e30f;
            }
        } else {
            #pragma unroll
            for (int t = 0; t < 8; t++)
                #pragma unroll
                for (int e = 0; e < 4; e++) s[t][e] *= scale;
        }

        // ---- online softmax ----
        float rm1 = -INFINITY, rm2 = -INFINITY;
        #pragma unroll
        for (int t = 0; t < 8; t++) {
            rm1 = fmaxf(rm1, fmaxf(s[t][0], s[t][1]));
            rm2 = fmaxf(rm2, fmaxf(s[t][2], s[t][3]));
        }
        rm1 = fmaxf(rm1, __shfl_xor_sync(0xffffffffu, rm1, 1));
        rm1 = fmaxf(rm1, __shfl_xor_sync(0xffffffffu, rm1, 2));
        rm2 = fmaxf(rm2, __shfl_xor_sync(0xffffffffu, rm2, 1));
        rm2 = fmaxf(rm2, __shfl_xor_sync(0xffffffffu, rm2, 2));
        float mn1 = fmaxf(m1, rm1), mn2 = fmaxf(m2, rm2);
        float cr1 = __expf(m1 - mn1), cr2 = __expf(m2 - mn2);
        m1 = mn1; m2 = mn2;
        float rs1 = 0.f, rs2 = 0.f;
        #pragma unroll
        for (int t = 0; t < 8; t++) {
            s[t][0] = __expf(s[t][0] - mn1);
            s[t][1] = __expf(s[t][1] - mn1);
            s[t][2] = __expf(s[t][2] - mn2);
            s[t][3] = __expf(s[t][3] - mn2);
            rs1 += s[t][0] + s[t][1];
            rs2 += s[t][2] + s[t][3];
        }
        rs1 += __shfl_xor_sync(0xffffffffu, rs1, 1);
        rs1 += __shfl_xor_sync(0xffffffffu, rs1, 2);
        rs2 += __shfl_xor_sync(0xffffffffu, rs2, 1);
        rs2 += __shfl_xor_sync(0xffffffffu, rs2, 2);
        l1 = l1 * cr1 + rs1;
        l2 = l2 * cr2 + rs2;
        #pragma unroll
        for (int t = 0; t < 16; t++) {
            o[t][0] *= cr1; o[t][1] *= cr1;
            o[t][2] *= cr2; o[t][3] *= cr2;
        }

        // ---- O += P V  (P split to hi/lo in registers) ----
        #pragma unroll
        for (int t = 0; t < 4; t++) {
            uint32_t pah[4], pal[4];
            float* s0 = s[2 * t];
            float* s1 = s[2 * t + 1];
            pah[0] = pack_bf16(s0[0], s0[1]);
            pah[1] = pack_bf16(s0[2], s0[3]);
            pah[2] = pack_bf16(s1[0], s1[1]);
            pah[3] = pack_bf16(s1[2], s1[3]);
            float q00 = s0[0] - __bfloat162float(__ushort_as_bfloat16((unsigned short)(pah[0] & 0xffff)));
            float q01 = s0[1] - __bfloat162float(__ushort_as_bfloat16((unsigned short)(pah[0] >> 16)));
            float q02 = s0[2] - __bfloat162float(__ushort_as_bfloat16((unsigned short)(pah[1] & 0xffff)));
            float q03 = s0[3] - __bfloat162float(__ushort_as_bfloat16((unsigned short)(pah[1] >> 16)));
            float q10 = s1[0] - __bfloat162float(__ushort_as_bfloat16((unsigned short)(pah[2] & 0xffff)));
            float q11 = s1[1] - __bfloat162float(__ushort_as_bfloat16((unsigned short)(pah[2] >> 16)));
            float q12 = s1[2] - __bfloat162float(__ushort_as_bfloat16((unsigned short)(pah[3] & 0xffff)));
            float q13 = s1[3] - __bfloat162float(__ushort_as_bfloat16((unsigned short)(pah[3] >> 16)));
            pal[0] = pack_bf16(q00, q01);
            pal[1] = pack_bf16(q02, q03);
            pal[2] = pack_bf16(q10, q11);
            pal[3] = pack_bf16(q12, q13);

            #pragma unroll
            for (int g = 0; g < 8; g++) {
                uint32_t bhv[4], blv[4];
                uint32_t rb = sb + TVH
                    + (uint32_t)(16 * t + (l & 7) + ((l >> 3) & 1) * 8) * LDB2
                    + 32 * g + ((l >> 4) & 1) * 16;
                ldsm4t(bhv, rb);
                ldsm4t(blv, rb + (TVL - TVH));
                mma16816(o[2 * g],     pah, bhv);
                mma16816(o[2 * g],     pal, bhv);
                mma16816(o[2 * g],     pah, blv);
                mma16816(o[2 * g + 1], pah, bhv + 2);
                mma16816(o[2 * g + 1], pal, bhv + 2);
                mma16816(o[2 * g + 1], pah, blv + 2);
            }
        }
    }

    // ---- epilogue: O /= l, write bf16 hi/lo planes at [B,S,NH*HD] ----
    float il1 = 1.f / l1, il2 = 1.f / l2;
    int b = bh >> 4, h = bh & (NH_ - 1);
    int sr = qt * 64 + w * 16 + (l >> 2);
    size_t base1 = ((size_t)(b * S_ + sr)) * H_ + h * HD_;
    size_t base2 = base1 + (size_t)8 * H_;
    #pragma unroll
    for (int t = 0; t < 16; t++) {
        int d = t * 8 + (l & 3) * 2;
        float v0 = o[t][0] * il1, v1 = o[t][1] * il1;
        float v2 = o[t][2] * il2, v3 = o[t][3] * il2;
        uint32_t h0 = pack_bf16(v0, v1);
        float w0 = v0 - __bfloat162float(__ushort_as_bfloat16((unsigned short)(h0 & 0xffff)));
        float w1 = v1 - __bfloat162float(__ushort_as_bfloat16((unsigned short)(h0 >> 16)));
        uint32_t h1 = pack_bf16(v2, v3);
        float w2 = v2 - __bfloat162float(__ushort_as_bfloat16((unsigned short)(h1 & 0xffff)));
        float w3 = v3 - __bfloat162float(__ushort_as_bfloat16((unsigned short)(h1 >> 16)));
        *(uint32_t*)&Ohi[base1 + d] = h0;
        *(uint32_t*)&Olo[base1 + d] = pack_bf16(w0, w1);
        *(uint32_t*)&Ohi[base2 + d] = h1;
        *(uint32_t*)&Olo[base2 + d] = pack_bf16(w2, w3);
    }
}

// ---------------------------------------------------------------------------
extern "C" void kernel_launch(void* const* d_in, const int* in_sizes, int n_in,
                              void* d_out, int out_size)
{
    const float* hidden = (const float*)d_in[0];
    const float* lastts = (const float*)d_in[1];
    const float* Wq     = (const float*)d_in[2];
    const float* Wk     = (const float*)d_in[3];
    const float* Wv     = (const float*)d_in[4];
    const float* Wo     = (const float*)d_in[5];
    const float* Wts    = (const float*)d_in[6];
    const float* tsw    = (const float*)d_in[7];
    const float* Worig  = (const float*)d_in[8];
    float* out = (float*)d_out;

    float *ts, *add, *qb, *kb, *vb;
    __nv_bfloat16 *Ahi, *Alo, *tsHi, *tsLo, *WHi, *WLo;
    __nv_bfloat16 *Qhi, *Qlo, *Khi, *Klo, *Vhi, *Vlo;
    cudaGetSymbolAddress((void**)&ts,   g_ts);
    cudaGetSymbolAddress((void**)&add,  g_add);
    cudaGetSymbolAddress((void**)&qb,   g_qb);
    cudaGetSymbolAddress((void**)&kb,   g_kb);
    cudaGetSymbolAddress((void**)&vb,   g_vb);
    cudaGetSymbolAddress((void**)&Ahi,  g_Ahi);
    cudaGetSymbolAddress((void**)&Alo,  g_Alo);
    cudaGetSymbolAddress((void**)&tsHi, g_tsHi);
    cudaGetSymbolAddress((void**)&tsLo, g_tsLo);
    cudaGetSymbolAddress((void**)&WHi,  g_WHi);
    cudaGetSymbolAddress((void**)&WLo,  g_WLo);
    cudaGetSymbolAddress((void**)&Qhi,  g_Qhi);
    cudaGetSymbolAddress((void**)&Qlo,  g_Qlo);
    cudaGetSymbolAddress((void**)&Khi,  g_Khi);
    cudaGetSymbolAddress((void**)&Klo,  g_Klo);
    cudaGetSymbolAddress((void**)&Vhi,  g_Vhi);
    cudaGetSymbolAddress((void**)&Vlo,  g_Vlo);

    cudaFuncSetAttribute(gemm_mma, cudaFuncAttributeMaxDynamicSharedMemorySize, GEMM_SMEM);
    cudaFuncSetAttribute(flash_mma, cudaFuncAttributeMaxDynamicSharedMemorySize, FLASH_SMEM2);

    // 0) converts: weights (transposed) + hidden
    dim3 tb(32, 8);
    convertBT_kernel<<<dim3(64, 64), tb>>>(Wq, 2048, 2048, WHi + WOFF_Q, WLo + WOFF_Q);
    convertBT_kernel<<<dim3(64, 64), tb>>>(Wk, 2048, 2048, WHi + WOFF_K, WLo + WOFF_K);
    convertBT_kernel<<<dim3(64, 64), tb>>>(Wv, 2048, 2048, WHi + WOFF_V, WLo + WOFF_V);
    convertBT_kernel<<<dim3(64, 64), tb>>>(Wo, 2048, 2048, WHi + WOFF_O, WLo + WOFF_O);
    convertBT_kernel<<<dim3(64, 16), tb>>>(Wts, 512, 2048, WHi + WOFF_TS, WLo + WOFF_TS);
    convertBT_kernel<<<dim3(16, 128), tb>>>(Worig, 6144, 512, WHi + WOFF_OR, WLo + WOFF_OR);
    convertA_kernel<<<(ROWS * H_ / 4 + 255) / 256, 256>>>(hidden, Ahi, Alo, ROWS * H_ / 4);

    // 1) ts = hidden @ Wts
    gemm_mma<<<dim3(4, 32), 256, GEMM_SMEM>>>(Ahi, Alo, WHi + WOFF_TS, WLo + WOFF_TS,
                                              nullptr, ts, 2048, 512, 0);
    // 2) blend + rmsnorm + kth + relu -> bf16 planes
    ts_rowops_kernel<<<ROWS, 512>>>(lastts, tsw, ts, tsHi, tsLo);
    // 3) add = ts @ Worig[:, :4096]
    gemm_mma<<<dim3(32, 32), 256, GEMM_SMEM>>>(tsHi, tsLo, WHi + WOFF_OR, WLo + WOFF_OR,
                                               nullptr, add, 512, 4096, 0);
    // 4) q/k/v
    gemm_mma<<<dim3(16, 32), 256, GEMM_SMEM>>>(Ahi, Alo, WHi + WOFF_Q, WLo + WOFF_Q,
                                               add,        qb, 2048, 2048, 4096);
    gemm_mma<<<dim3(16, 32), 256, GEMM_SMEM>>>(Ahi, Alo, WHi + WOFF_K, WLo + WOFF_K,
                                               add + 2048, kb, 2048, 2048, 4096);
    gemm_mma<<<dim3(16, 32), 256, GEMM_SMEM>>>(Ahi, Alo, WHi + WOFF_V, WLo + WOFF_V,
                                               add + 2048, vb, 2048, 2048, 4096);
    // 5) RoPE + transpose -> bf16 hi/lo planes
    int tot = ROWS * NH_ * 64;
    rope_transpose_kernel<<<(tot + 255) / 256, 256>>>(qb, kb, vb,
                                                      Qhi, Qlo, Khi, Klo, Vhi, Vlo);
    // 6) causal flash attention on tensor pipe -> attn bf16 planes (reuse Ahi/Alo)
    flash_mma<<<dim3(S_ / 64, B_ * NH_), 128, FLASH_SMEM2>>>(Qhi, Qlo, Khi, Klo, Vhi, Vlo,
                                                             Ahi, Alo);
    // 7) out = attn @ Wo
    gemm_mma<<<dim3(16, 32), 256, GEMM_SMEM>>>(Ahi, Alo, WHi + WOFF_O, WLo + WOFF_O,
                                               nullptr, out, 2048, 2048, 0);
}

// round 7
// speedup vs baseline: 2.0676x; 1.1080x over previous
#include <cuda_runtime.h>
#include <cuda_bf16.h>
#include <math.h>
#include <stdint.h>

#define B_   2
#define S_   2048
#define H_   2048
#define NH_  16
#define HD_  128
#define TS_  512
#define ROWS (B_*S_)        // 4096
#define KIDX 460

// ------------------------- mma.sync helpers (baseline PTX) -----------------
__device__ __forceinline__ uint32_t smem_u32(const void* p) {
    uint32_t a;
    asm("{ .reg .u64 t; cvta.to.shared.u64 t,%1; cvt.u32.u64 %0,t; }" : "=r"(a) : "l"(p));
    return a;
}
__device__ __forceinline__ void ldsm4(uint32_t* r, uint32_t addr) {
    asm volatile("ldmatrix.sync.aligned.m8n8.x4.shared.b16 {%0,%1,%2,%3},[%4];"
        : "=r"(r[0]), "=r"(r[1]), "=r"(r[2]), "=r"(r[3]) : "r"(addr));
}
__device__ __forceinline__ void ldsm4t(uint32_t* r, uint32_t addr) {
    asm volatile("ldmatrix.sync.aligned.m8n8.x4.trans.shared.b16 {%0,%1,%2,%3},[%4];"
        : "=r"(r[0]), "=r"(r[1]), "=r"(r[2]), "=r"(r[3]) : "r"(addr));
}
__device__ __forceinline__ void mma16816(float* c, const uint32_t* a, const uint32_t* b) {
    asm volatile(
        "mma.sync.aligned.m16n8k16.row.col.f32.bf16.bf16.f32 "
        "{%0,%1,%2,%3},{%4,%5,%6,%7},{%8,%9},{%0,%1,%2,%3};"
        : "+f"(c[0]), "+f"(c[1]), "+f"(c[2]), "+f"(c[3])
        : "r"(a[0]), "r"(a[1]), "r"(a[2]), "r"(a[3]), "r"(b[0]), "r"(b[1]));
}
__device__ __forceinline__ uint32_t pack_bf16(float a, float b) {
    __nv_bfloat16 ha = __float2bfloat16_rn(a), hb = __float2bfloat16_rn(b);
    return (uint32_t)__bfloat16_as_ushort(ha) | ((uint32_t)__bfloat16_as_ushort(hb) << 16);
}
__device__ __forceinline__ void split_store(float v, __nv_bfloat16* hi, __nv_bfloat16* lo, size_t idx) {
    __nv_bfloat16 h = __float2bfloat16_rn(v);
    hi[idx] = h;
    lo[idx] = __float2bfloat16_rn(v - __bfloat162float(h));
}
// cp.async
__device__ __forceinline__ void cpa16(uint32_t dst, const void* src) {
    asm volatile("cp.async.cg.shared.global [%0],[%1],16;" :: "r"(dst), "l"(src));
}
#define CPA_COMMIT() asm volatile("cp.async.commit_group;" ::: "memory")
#define CPA_WAIT1()  asm volatile("cp.async.wait_group 1;" ::: "memory")
#define CPA_WAIT0()  asm volatile("cp.async.wait_group 0;" ::: "memory")

// ---------------- scratch (device globals) ---------------------------------
__device__ float g_ts[(size_t)ROWS * TS_];
__device__ float g_add[(size_t)ROWS * 4096];
__device__ float g_qkv[(size_t)ROWS * 6144];      // [q|k|v] fused GEMM output
__device__ float g_invf[64];

__device__ __nv_bfloat16 g_Ahi[(size_t)ROWS * H_];   // hidden, later attn-out
__device__ __nv_bfloat16 g_Alo[(size_t)ROWS * H_];
__device__ __nv_bfloat16 g_tsHi[(size_t)ROWS * TS_];
__device__ __nv_bfloat16 g_tsLo[(size_t)ROWS * TS_];
__device__ __nv_bfloat16 g_Qhi[(size_t)ROWS * H_];
__device__ __nv_bfloat16 g_Qlo[(size_t)ROWS * H_];
__device__ __nv_bfloat16 g_Khi[(size_t)ROWS * H_];
__device__ __nv_bfloat16 g_Klo[(size_t)ROWS * H_];
__device__ __nv_bfloat16 g_Vhi[(size_t)ROWS * H_];
__device__ __nv_bfloat16 g_Vlo[(size_t)ROWS * H_];

#define WOFF_Q  ((size_t)0)
#define WOFF_K  ((size_t)4194304)
#define WOFF_V  ((size_t)8388608)
#define WOFF_O  ((size_t)12582912)
#define WOFF_TS ((size_t)16777216)
#define WOFF_OR ((size_t)17825792)
#define WTOTAL  ((size_t)19922944)
__device__ __nv_bfloat16 g_WHi[WTOTAL];
__device__ __nv_bfloat16 g_WLo[WTOTAL];

// ---------------- init: 64 inv-freq values (double exp ONCE) ---------------
__global__ void init_invf_kernel() {
    int d = threadIdx.x;
    if (d < 64) g_invf[d] = (float)exp(-(double)d * (9.210340371976184 / 64.0));
}

// ---------------- convert kernels ------------------------------------------
__global__ void convertA_kernel(const float* __restrict__ src,
                                __nv_bfloat16* __restrict__ hi,
                                __nv_bfloat16* __restrict__ lo, int n4)
{
    int i = blockIdx.x * blockDim.x + threadIdx.x;
    if (i >= n4) return;
    float4 v = ((const float4*)src)[i];
    __nv_bfloat16 h0 = __float2bfloat16(v.x);
    __nv_bfloat16 h1 = __float2bfloat16(v.y);
    __nv_bfloat16 h2 = __float2bfloat16(v.z);
    __nv_bfloat16 h3 = __float2bfloat16(v.w);
    __nv_bfloat16 l0 = __float2bfloat16(v.x - __bfloat162float(h0));
    __nv_bfloat16 l1 = __float2bfloat16(v.y - __bfloat162float(h1));
    __nv_bfloat16 l2 = __float2bfloat16(v.z - __bfloat162float(h2));
    __nv_bfloat16 l3 = __float2bfloat16(v.w - __bfloat162float(h3));
    ushort4 hv = make_ushort4(__bfloat16_as_ushort(h0), __bfloat16_as_ushort(h1),
                              __bfloat16_as_ushort(h2), __bfloat16_as_ushort(h3));
    ushort4 lv = make_ushort4(__bfloat16_as_ushort(l0), __bfloat16_as_ushort(l1),
                              __bfloat16_as_ushort(l2), __bfloat16_as_ushort(l3));
    ((ushort4*)hi)[i] = hv;
    ((ushort4*)lo)[i] = lv;
}

__global__ void convertBT_kernel(const float* __restrict__ src, int ld, int Kdim,
                                 __nv_bfloat16* __restrict__ hi,
                                 __nv_bfloat16* __restrict__ lo)
{
    __shared__ float t[32][33];
    int tx = threadIdx.x, ty = threadIdx.y;
    int k0 = blockIdx.x * 32, n0 = blockIdx.y * 32;
    #pragma unroll
    for (int i = 0; i < 4; i++)
        t[ty + 8 * i][tx] = src[(size_t)(k0 + ty + 8 * i) * ld + n0 + tx];
    __syncthreads();
    #pragma unroll
    for (int i = 0; i < 4; i++) {
        float v = t[tx][ty + 8 * i];
        __nv_bfloat16 h = __float2bfloat16(v);
        __nv_bfloat16 l = __float2bfloat16(v - __bfloat162float(h));
        size_t o = (size_t)(n0 + ty + 8 * i) * Kdim + k0 + tx;
        hi[o] = h; lo[o] = l;
    }
}

// ---------------- HMMA GEMM: C[M,N] = A @ B^T (+Add, col-wrapped) ----------
#define LDT    40
#define PLSZ   (128*LDT*2)
#define BUFSZ  (4*PLSZ)
#define GEMM_SMEM (2*BUFSZ)

__global__ __launch_bounds__(256) void gemm_mma(
    const __nv_bfloat16* __restrict__ Ahi, const __nv_bfloat16* __restrict__ Alo,
    const __nv_bfloat16* __restrict__ Bhi, const __nv_bfloat16* __restrict__ Blo,
    const float* __restrict__ Add, float* __restrict__ C,
    int K, int N, int ldadd)
{
    extern __shared__ char smc[];
    uint32_t sb = smem_u32(smc);
    int tid = threadIdx.x, lane = tid & 31, wid = tid >> 5;
    int wm = wid >> 2, wn = wid & 3;
    int tile_n = blockIdx.x * 128, tile_m = blockIdx.y * 128;

    int lrow = tid & 127, plane = tid >> 7;
    const uint4* Ag = (const uint4*)((plane ? Alo : Ahi) + (size_t)(tile_m + lrow) * K);
    const uint4* Bg = (const uint4*)((plane ? Blo : Bhi) + (size_t)(tile_n + lrow) * K);
    uint32_t dstA = sb + plane * PLSZ + lrow * (LDT * 2);
    uint32_t dstB = dstA + 2 * PLSZ;

    float acc[4][4][4];
    #pragma unroll
    for (int i = 0; i < 4; i++)
        #pragma unroll
        for (int j = 0; j < 4; j++)
            #pragma unroll
            for (int e = 0; e < 4; e++) acc[i][j][e] = 0.f;

    int nch = K >> 5;

    // issue chunks 0 and 1
    #pragma unroll
    for (int j = 0; j < 4; j++) {
        cpa16(dstA + j * 16, Ag + j);
        cpa16(dstB + j * 16, Bg + j);
    }
    CPA_COMMIT();
    #pragma unroll
    for (int j = 0; j < 4; j++) {
        cpa16(dstA + BUFSZ + j * 16, Ag + 4 + j);
        cpa16(dstB + BUFSZ + j * 16, Bg + 4 + j);
    }
    CPA_COMMIT();

    for (int c = 0; c < nch; c++) {
        if (c + 1 < nch) { CPA_WAIT1(); } else { CPA_WAIT0(); }
        __syncthreads();

        uint32_t base = sb + (c & 1) * BUFSZ;
        #pragma unroll
        for (int s = 0; s < 2; s++) {
            uint32_t bh[4][2], bl[4][2];
            #pragma unroll
            for (int jp = 0; jp < 2; jp++) {
                uint32_t nloc = (uint32_t)(wn * 32 + jp * 16 + ((lane >> 4) & 1) * 8 + (lane & 7));
                uint32_t off = nloc * 80 + s * 32 + ((lane >> 3) & 1) * 16;
                uint32_t t[4];
                ldsm4(t, base + 2 * PLSZ + off);
                bh[jp * 2][0] = t[0]; bh[jp * 2][1] = t[1];
                bh[jp * 2 + 1][0] = t[2]; bh[jp * 2 + 1][1] = t[3];
                ldsm4(t, base + 3 * PLSZ + off);
                bl[jp * 2][0] = t[0]; bl[jp * 2][1] = t[1];
                bl[jp * 2 + 1][0] = t[2]; bl[jp * 2 + 1][1] = t[3];
            }
            #pragma unroll
            for (int i = 0; i < 4; i++) {
                uint32_t ra = (uint32_t)(wm * 64 + i * 16 + (lane & 7) + ((lane >> 3) & 1) * 8) * 80
                            + s * 32 + ((lane >> 4) & 1) * 16;
                uint32_t ah[4], al[4];
                ldsm4(ah, base + ra);
                ldsm4(al, base + PLSZ + ra);
                #pragma unroll
                for (int j = 0; j < 4; j++) {
                    mma16816(acc[i][j], ah, bh[j]);
                    mma16816(acc[i][j], al, bh[j]);
                    mma16816(acc[i][j], ah, bl[j]);
                }
            }
        }
        __syncthreads();

        if (c + 2 < nch) {
            uint32_t dA = dstA + (c & 1) * BUFSZ;
            uint32_t dB = dstB + (c & 1) * BUFSZ;
            const uint4* a = Ag + (size_t)(c + 2) * 4;
            const uint4* b = Bg + (size_t)(c + 2) * 4;
            #pragma unroll
            for (int j = 0; j < 4; j++) {
                cpa16(dA + j * 16, a + j);
                cpa16(dB + j * 16, b + j);
            }
            CPA_COMMIT();
        }
    }

    // epilogue (+Add with column wrap: cols >= 4096 reuse k_add slice)
    int addn = (tile_n >= 4096) ? tile_n - 2048 : tile_n;
    #pragma unroll
    for (int i = 0; i < 4; i++) {
        int row = tile_m + wm * 64 + i * 16 + (lane >> 2);
        #pragma unroll
        for (int j = 0; j < 4; j++) {
            int loc = wn * 32 + j * 8 + (lane & 3) * 2;
            float2 v0 = make_float2(acc[i][j][0], acc[i][j][1]);
            float2 v1 = make_float2(acc[i][j][2], acc[i][j][3]);
            if (Add) {
                float2 a0 = *(const float2*)&Add[(size_t)row * ldadd + addn + loc];
                float2 a1 = *(const float2*)&Add[(size_t)(row + 8) * ldadd + addn + loc];
                v0.x += a0.x; v0.y += a0.y;
                v1.x += a1.x; v1.y += a1.y;
            }
            *(float2*)&C[(size_t)row * N + tile_n + loc] = v0;
            *(float2*)&C[(size_t)(row + 8) * N + tile_n + loc] = v1;
        }
    }
}

// -------- blend + rmsnorm + exact k-th + relu-shift; writes bf16 planes ----
__global__ __launch_bounds__(512) void ts_rowops_kernel(
    const float* __restrict__ last, const float* __restrict__ w,
    const float* __restrict__ ts,
    __nv_bfloat16* __restrict__ tsHi, __nv_bfloat16* __restrict__ tsLo)
{
    __shared__ float sv[512];
    __shared__ float rbuf[512];
    int row = blockIdx.x;
    int j = threadIdx.x;
    size_t idx = (size_t)row * TS_ + j;

    float x = 0.5f * ts[idx] + 0.5f * last[idx];
    rbuf[j] = x * x;
    __syncthreads();
    #pragma unroll
    for (int s2 = 256; s2 > 0; s2 >>= 1) {
        if (j < s2) rbuf[j] += rbuf[j + s2];
        __syncthreads();
    }
    float var = rbuf[0] * (1.f / 512.f);
    float y = x * rsqrtf(var + 1e-6f) * w[j];
    sv[j] = y;
    __syncthreads();

    for (int k = 2; k <= 512; k <<= 1) {
        for (int jj = k >> 1; jj > 0; jj >>= 1) {
            int ixj = j ^ jj;
            if (ixj > j) {
                float a = sv[j], b = sv[ixj];
                bool asc = ((j & k) == 0);
                if (asc ? (a > b) : (a < b)) { sv[j] = b; sv[ixj] = a; }
            }
            __syncthreads();
        }
    }
    float kth = sv[KIDX - 1];
    split_store(fmaxf(y - kth, 0.f), tsHi, tsLo, idx);
}

// ------- RoPE + transpose to head-major bf16 hi/lo planes [B,NH,S,HD] ------
__global__ void rope_transpose_kernel(
    const float* __restrict__ qkv,
    __nv_bfloat16* __restrict__ Qhi, __nv_bfloat16* __restrict__ Qlo,
    __nv_bfloat16* __restrict__ Khi, __nv_bfloat16* __restrict__ Klo,
    __nv_bfloat16* __restrict__ Vhi, __nv_bfloat16* __restrict__ Vlo)
{
    int i = blockIdx.x * blockDim.x + threadIdx.x;
    if (i >= ROWS * NH_ * 64) return;
    int d = i & 63;
    int h = (i >> 6) & (NH_ - 1);
    int row = i >> 10;
    int b = row >> 11;
    int s = row & (S_ - 1);

    float inv = g_invf[d];
    float ang = (float)s * inv;
    float cs, sn;
    sincosf(ang, &sn, &cs);

    size_t src = (size_t)row * 6144 + h * HD_ + d;
    float q0 = qkv[src],        q1 = qkv[src + 64];
    float k0 = qkv[src + 2048], k1 = qkv[src + 2048 + 64];
    float v0 = qkv[src + 4096], v1 = qkv[src + 4096 + 64];
    size_t dst = ((size_t)(b * NH_ + h) * S_ + s) * HD_ + d;
    split_store(q0 * cs - q1 * sn, Qhi, Qlo, dst);
    split_store(q1 * cs + q0 * sn, Qhi, Qlo, dst + 64);
    split_store(k0 * cs - k1 * sn, Khi, Klo, dst);
    split_store(k1 * cs + k0 * sn, Khi, Klo, dst + 64);
    split_store(v0, Vhi, Vlo, dst);
    split_store(v1, Vhi, Vlo, dst + 64);
}

// ---------------- flash attention on mma.sync (bf16 split) -----------------
#define LDB2  272
#define TQH   0
#define TQL   17408
#define TKH   34816
#define TKL   52224
#define TVH   69632
#define TVL   87040
#define FLASH_SMEM2 104448

__global__ __launch_bounds__(128) void flash_mma(
    const __nv_bfloat16* __restrict__ Qhi, const __nv_bfloat16* __restrict__ Qlo,
    const __nv_bfloat16* __restrict__ Khi, const __nv_bfloat16* __restrict__ Klo,
    const __nv_bfloat16* __restrict__ Vhi, const __nv_bfloat16* __restrict__ Vlo,
    __nv_bfloat16* __restrict__ Ohi, __nv_bfloat16* __restrict__ Olo)
{
    extern __shared__ char sm[];
    uint32_t sb = smem_u32(sm);
    int tid = threadIdx.x, l = tid & 31, w = tid >> 5;
    int qt = blockIdx.x, bh = blockIdx.y;
    size_t bhS = (size_t)bh * S_;

    for (int i = tid; i < 2048; i += 128) {
        int plane = i >> 10, rem = i & 1023, row = rem >> 4, c = rem & 15;
        const uint4* src = (const uint4*)((plane ? Qlo : Qhi) + (bhS + (size_t)qt * 64 + row) * HD_);
        *(uint4*)(sm + (plane ? TQL : TQH) + row * LDB2 + c * 16) = src[c];
    }

    float o[16][4];
    #pragma unroll
    for (int t = 0; t < 16; t++)
        #pragma unroll
        for (int e = 0; e < 4; e++) o[t][e] = 0.f;
    float m1 = -INFINITY, m2 = -INFINITY, l1 = 0.f, l2 = 0.f;
    const float scale = 0.08838834764831845f;

    for (int kt = 0; kt <= qt; kt++) {
        __syncthreads();
        for (int i = tid; i < 4096; i += 128) {
            int plane = i >> 10, rem = i & 1023, row = rem >> 4, c = rem & 15;
            const __nv_bfloat16* bp = (plane == 0) ? Khi : (plane == 1) ? Klo
                                      : (plane == 2) ? Vhi : Vlo;
            const uint4* src = (const uint4*)(bp + (bhS + (size_t)kt * 64 + row) * HD_);
            uint32_t off = (plane == 0) ? TKH : (plane == 1) ? TKL : (plane == 2) ? TVH : TVL;
            *(uint4*)(sm + off + row * LDB2 + c * 16) = src[c];
        }
        __syncthreads();

        float s[8][4];
        #pragma unroll
        for (int t = 0; t < 8; t++)
            #pragma unroll
            for (int e = 0; e < 4; e++) s[t][e] = 0.f;

        #pragma unroll
        for (int kk = 0; kk < 8; kk++) {
            uint32_t ah[4], al[4];
            uint32_t ra = sb + TQH + (uint32_t)(w * 16 + (l & 15)) * LDB2
                        + ((l >> 4) & 1) * 16 + kk * 32;
            ldsm4(ah, ra);
            ldsm4(al, ra + (TQL - TQH));
            #pragma unroll
            for (int g = 0; g < 4; g++) {
                uint32_t bhv[4], blv[4];
                uint32_t rb = sb + TKH
                    + (uint32_t)(16 * g + (l & 7) + ((l >> 4) & 1) * 8) * LDB2
                    + ((l >> 3) & 1) * 16 + kk * 32;
                ldsm4(bhv, rb);
                ldsm4(blv, rb + (TKL - TKH));
                mma16816(s[2 * g],     ah, bhv);
                mma16816(s[2 * g],     al, bhv);
                mma16816(s[2 * g],     ah, blv);
                mma16816(s[2 * g + 1], ah, bhv + 2);
                mma16816(s[2 * g + 1], al, bhv + 2);
                mma16816(s[2 * g + 1], ah, blv + 2);
            }
        }

        int r1 = (qt << 6) + w * 16 + (l >> 2), r2 = r1 + 8;
        int cb = (kt << 6) + ((l & 3) << 1);
        if (kt == qt) {
            #pragma unroll
            for (int t = 0; t < 8; t++) {
                int c0 = cb + t * 8, c1 = c0 + 1;
                s[t][0] = (c0 <= r1) ? s[t][0] * scale : -1e30f;
                s[t][1] = (c1 <= r1) ? s[t][1] * scale : -1e30f;
                s[t][2] = (c0 <= r2) ? s[t][2] * scale : -1e30f;
                s[t][3] = (c1 <= r2) ? s[t][3] * scale : -1e30f;
            }
        } else {
            #pragma unroll
            for (int t = 0; t < 8; t++)
                #pragma unroll
                for (int e = 0; e < 4; e++) s[t][e] *= scale;
        }

        float rm1 = -INFINITY, rm2 = -INFINITY;
        #pragma unroll
        for (int t = 0; t < 8; t++) {
            rm1 = fmaxf(rm1, fmaxf(s[t][0], s[t][1]));
            rm2 = fmaxf(rm2, fmaxf(s[t][2], s[t][3]));
        }
        rm1 = fmaxf(rm1, __shfl_xor_sync(0xffffffffu, rm1, 1));
        rm1 = fmaxf(rm1, __shfl_xor_sync(0xffffffffu, rm1, 2));
        rm2 = fmaxf(rm2, __shfl_xor_sync(0xffffffffu, rm2, 1));
        rm2 = fmaxf(rm2, __shfl_xor_sync(0xffffffffu, rm2, 2));
        float mn1 = fmaxf(m1, rm1), mn2 = fmaxf(m2, rm2);
        float cr1 = __expf(m1 - mn1), cr2 = __expf(m2 - mn2);
        m1 = mn1; m2 = mn2;
        float rs1 = 0.f, rs2 = 0.f;
        #pragma unroll
        for (int t = 0; t < 8; t++) {
            s[t][0] = __expf(s[t][0] - mn1);
            s[t][1] = __expf(s[t][1] - mn1);
            s[t][2] = __expf(s[t][2] - mn2);
            s[t][3] = __expf(s[t][3] - mn2);
            rs1 += s[t][0] + s[t][1];
            rs2 += s[t][2] + s[t][3];
        }
        rs1 += __shfl_xor_sync(0xffffffffu, rs1, 1);
        rs1 += __shfl_xor_sync(0xffffffffu, rs1, 2);
        rs2 += __shfl_xor_sync(0xffffffffu, rs2, 1);
        rs2 += __shfl_xor_sync(0xffffffffu, rs2, 2);
        l1 = l1 * cr1 + rs1;
        l2 = l2 * cr2 + rs2;
        #pragma unroll
        for (int t = 0; t < 16; t++) {
            o[t][0] *= cr1; o[t][1] *= cr1;
            o[t][2] *= cr2; o[t][3] *= cr2;
        }

        #pragma unroll
        for (int t = 0; t < 4; t++) {
            uint32_t pah[4], pal[4];
            float* s0 = s[2 * t];
            float* s1 = s[2 * t + 1];
            pah[0] = pack_bf16(s0[0], s0[1]);
            pah[1] = pack_bf16(s0[2], s0[3]);
            pah[2] = pack_bf16(s1[0], s1[1]);
            pah[3] = pack_bf16(s1[2], s1[3]);
            float q00 = s0[0] - __bfloat162float(__ushort_as_bfloat16((unsigned short)(pah[0] & 0xffff)));
            float q01 = s0[1] - __bfloat162float(__ushort_as_bfloat16((unsigned short)(pah[0] >> 16)));
            float q02 = s0[2] - __bfloat162float(__ushort_as_bfloat16((unsigned short)(pah[1] & 0xffff)));
            float q03 = s0[3] - __bfloat162float(__ushort_as_bfloat16((unsigned short)(pah[1] >> 16)));
            float q10 = s1[0] - __bfloat162float(__ushort_as_bfloat16((unsigned short)(pah[2] & 0xffff)));
            float q11 = s1[1] - __bfloat162float(__ushort_as_bfloat16((unsigned short)(pah[2] >> 16)));
            float q12 = s1[2] - __bfloat162float(__ushort_as_bfloat16((unsigned short)(pah[3] & 0xffff)));
            float q13 = s1[3] - __bfloat162float(__ushort_as_bfloat16((unsigned short)(pah[3] >> 16)));
            pal[0] = pack_bf16(q00, q01);
            pal[1] = pack_bf16(q02, q03);
            pal[2] = pack_bf16(q10, q11);
            pal[3] = pack_bf16(q12, q13);

            #pragma unroll
            for (int g = 0; g < 8; g++) {
                uint32_t bhv[4], blv[4];
                uint32_t rb = sb + TVH
                    + (uint32_t)(16 * t + (l & 7) + ((l >> 3) & 1) * 8) * LDB2
                    + 32 * g + ((l >> 4) & 1) * 16;
                ldsm4t(bhv, rb);
                ldsm4t(blv, rb + (TVL - TVH));
                mma16816(o[2 * g],     pah, bhv);
                mma16816(o[2 * g],     pal, bhv);
                mma16816(o[2 * g],     pah, blv);
                mma16816(o[2 * g + 1], pah, bhv + 2);
                mma16816(o[2 * g + 1], pal, bhv + 2);
                mma16816(o[2 * g + 1], pah, blv + 2);
            }
        }
    }

    float il1 = 1.f / l1, il2 = 1.f / l2;
    int b = bh >> 4, h = bh & (NH_ - 1);
    int sr = qt * 64 + w * 16 + (l >> 2);
    size_t base1 = ((size_t)(b * S_ + sr)) * H_ + h * HD_;
    size_t base2 = base1 + (size_t)8 * H_;
    #pragma unroll
    for (int t = 0; t < 16; t++) {
        int d = t * 8 + (l & 3) * 2;
        float v0 = o[t][0] * il1, v1 = o[t][1] * il1;
        float v2 = o[t][2] * il2, v3 = o[t][3] * il2;
        uint32_t h0 = pack_bf16(v0, v1);
        float w0 = v0 - __bfloat162float(__ushort_as_bfloat16((unsigned short)(h0 & 0xffff)));
        float w1 = v1 - __bfloat162float(__ushort_as_bfloat16((unsigned short)(h0 >> 16)));
        uint32_t h1 = pack_bf16(v2, v3);
        float w2 = v2 - __bfloat162float(__ushort_as_bfloat16((unsigned short)(h1 & 0xffff)));
        float w3 = v3 - __bfloat162float(__ushort_as_bfloat16((unsigned short)(h1 >> 16)));
        *(uint32_t*)&Ohi[base1 + d] = h0;
        *(uint32_t*)&Olo[base1 + d] = pack_bf16(w0, w1);
        *(uint32_t*)&Ohi[base2 + d] = h1;
        *(uint32_t*)&Olo[base2 + d] = pack_bf16(w2, w3);
    }
}

// ---------------------------------------------------------------------------
extern "C" void kernel_launch(void* const* d_in, const int* in_sizes, int n_in,
                              void* d_out, int out_size)
{
    const float* hidden = (const float*)d_in[0];
    const float* lastts = (const float*)d_in[1];
    const float* Wq     = (const float*)d_in[2];
    const float* Wk     = (const float*)d_in[3];
    const float* Wv     = (const float*)d_in[4];
    const float* Wo     = (const float*)d_in[5];
    const float* Wts    = (const float*)d_in[6];
    const float* tsw    = (const float*)d_in[7];
    const float* Worig  = (const float*)d_in[8];
    float* out = (float*)d_out;

    float *ts, *add, *qkv;
    __nv_bfloat16 *Ahi, *Alo, *tsHi, *tsLo, *WHi, *WLo;
    __nv_bfloat16 *Qhi, *Qlo, *Khi, *Klo, *Vhi, *Vlo;
    cudaGetSymbolAddress((void**)&ts,   g_ts);
    cudaGetSymbolAddress((void**)&add,  g_add);
    cudaGetSymbolAddress((void**)&qkv,  g_qkv);
    cudaGetSymbolAddress((void**)&Ahi,  g_Ahi);
    cudaGetSymbolAddress((void**)&Alo,  g_Alo);
    cudaGetSymbolAddress((void**)&tsHi, g_tsHi);
    cudaGetSymbolAddress((void**)&tsLo, g_tsLo);
    cudaGetSymbolAddress((void**)&WHi,  g_WHi);
    cudaGetSymbolAddress((void**)&WLo,  g_WLo);
    cudaGetSymbolAddress((void**)&Qhi,  g_Qhi);
    cudaGetSymbolAddress((void**)&Qlo,  g_Qlo);
    cudaGetSymbolAddress((void**)&Khi,  g_Khi);
    cudaGetSymbolAddress((void**)&Klo,  g_Klo);
    cudaGetSymbolAddress((void**)&Vhi,  g_Vhi);
    cudaGetSymbolAddress((void**)&Vlo,  g_Vlo);

    cudaFuncSetAttribute(gemm_mma, cudaFuncAttributeMaxDynamicSharedMemorySize, GEMM_SMEM);
    cudaFuncSetAttribute(flash_mma, cudaFuncAttributeMaxDynamicSharedMemorySize, FLASH_SMEM2);

    dim3 tb(32, 8);
    // launch order arranged so 0-based launch #5 is the origin GEMM (ncu -s 5)
    convertA_kernel<<<(ROWS * H_ / 4 + 255) / 256, 256>>>(hidden, Ahi, Alo, ROWS * H_ / 4); // 0
    convertBT_kernel<<<dim3(64, 16), tb>>>(Wts, 512, 2048, WHi + WOFF_TS, WLo + WOFF_TS);   // 1
    gemm_mma<<<dim3(4, 32), 256, GEMM_SMEM>>>(Ahi, Alo, WHi + WOFF_TS, WLo + WOFF_TS,
                                              nullptr, ts, 2048, 512, 0);                   // 2
    ts_rowops_kernel<<<ROWS, 512>>>(lastts, tsw, ts, tsHi, tsLo);                           // 3
    convertBT_kernel<<<dim3(16, 128), tb>>>(Worig, 6144, 512, WHi + WOFF_OR, WLo + WOFF_OR);// 4
    gemm_mma<<<dim3(32, 32), 256, GEMM_SMEM>>>(tsHi, tsLo, WHi + WOFF_OR, WLo + WOFF_OR,
                                               nullptr, add, 512, 4096, 0);                 // 5 <- profiled
    init_invf_kernel<<<1, 64>>>();                                                          // 6
    convertBT_kernel<<<dim3(64, 64), tb>>>(Wq, 2048, 2048, WHi + WOFF_Q, WLo + WOFF_Q);     // 7
    convertBT_kernel<<<dim3(64, 64), tb>>>(Wk, 2048, 2048, WHi + WOFF_K, WLo + WOFF_K);     // 8
    convertBT_kernel<<<dim3(64, 64), tb>>>(Wv, 2048, 2048, WHi + WOFF_V, WLo + WOFF_V);     // 9
    // fused QKV GEMM: N = 6144 (weights contiguous), Add column-wrapped
    gemm_mma<<<dim3(48, 32), 256, GEMM_SMEM>>>(Ahi, Alo, WHi + WOFF_Q, WLo + WOFF_Q,
                                               add, qkv, 2048, 6144, 4096);                 // 10
    int tot = ROWS * NH_ * 64;
    rope_transpose_kernel<<<(tot + 255) / 256, 256>>>(qkv, Qhi, Qlo, Khi, Klo, Vhi, Vlo);   // 11
    flash_mma<<<dim3(S_ / 64, B_ * NH_), 128, FLASH_SMEM2>>>(Qhi, Qlo, Khi, Klo, Vhi, Vlo,
                                                             Ahi, Alo);                     // 12
    convertBT_kernel<<<dim3(64, 64), tb>>>(Wo, 2048, 2048, WHi + WOFF_O, WLo + WOFF_O);     // 13
    gemm_mma<<<dim3(16, 32), 256, GEMM_SMEM>>>(Ahi, Alo, WHi + WOFF_O, WLo + WOFF_O,
                                               nullptr, out, 2048, 2048, 0);                // 14
}

// round 8
// speedup vs baseline: 2.3388x; 1.1312x over previous
#include <cuda_runtime.h>
#include <cuda_bf16.h>
#include <math.h>
#include <stdint.h>

#define B_   2
#define S_   2048
#define H_   2048
#define NH_  16
#define HD_  128
#define TS_  512
#define ROWS (B_*S_)        // 4096
#define KIDX 460

// ------------------------- mma.sync helpers (baseline PTX) -----------------
__device__ __forceinline__ uint32_t smem_u32(const void* p) {
    uint32_t a;
    asm("{ .reg .u64 t; cvta.to.shared.u64 t,%1; cvt.u32.u64 %0,t; }" : "=r"(a) : "l"(p));
    return a;
}
__device__ __forceinline__ void ldsm4(uint32_t* r, uint32_t addr) {
    asm volatile("ldmatrix.sync.aligned.m8n8.x4.shared.b16 {%0,%1,%2,%3},[%4];"
        : "=r"(r[0]), "=r"(r[1]), "=r"(r[2]), "=r"(r[3]) : "r"(addr));
}
__device__ __forceinline__ void ldsm4t(uint32_t* r, uint32_t addr) {
    asm volatile("ldmatrix.sync.aligned.m8n8.x4.trans.shared.b16 {%0,%1,%2,%3},[%4];"
        : "=r"(r[0]), "=r"(r[1]), "=r"(r[2]), "=r"(r[3]) : "r"(addr));
}
__device__ __forceinline__ void mma16816(float* c, const uint32_t* a, const uint32_t* b) {
    asm volatile(
        "mma.sync.aligned.m16n8k16.row.col.f32.bf16.bf16.f32 "
        "{%0,%1,%2,%3},{%4,%5,%6,%7},{%8,%9},{%0,%1,%2,%3};"
        : "+f"(c[0]), "+f"(c[1]), "+f"(c[2]), "+f"(c[3])
        : "r"(a[0]), "r"(a[1]), "r"(a[2]), "r"(a[3]), "r"(b[0]), "r"(b[1]));
}
__device__ __forceinline__ uint32_t pack_bf16(float a, float b) {
    __nv_bfloat16 ha = __float2bfloat16_rn(a), hb = __float2bfloat16_rn(b);
    return (uint32_t)__bfloat16_as_ushort(ha) | ((uint32_t)__bfloat16_as_ushort(hb) << 16);
}
__device__ __forceinline__ void split_store(float v, __nv_bfloat16* hi, __nv_bfloat16* lo, size_t idx) {
    __nv_bfloat16 h = __float2bfloat16_rn(v);
    hi[idx] = h;
    lo[idx] = __float2bfloat16_rn(v - __bfloat162float(h));
}
__device__ __forceinline__ void cpa16(uint32_t dst, const void* src) {
    asm volatile("cp.async.cg.shared.global [%0],[%1],16;" :: "r"(dst), "l"(src));
}
#define CPA_COMMIT() asm volatile("cp.async.commit_group;" ::: "memory")
#define CPA_WAIT1()  asm volatile("cp.async.wait_group 1;" ::: "memory")
#define CPA_WAIT0()  asm volatile("cp.async.wait_group 0;" ::: "memory")

// ---------------- scratch (device globals) ---------------------------------
__device__ float g_ts[(size_t)ROWS * TS_];
__device__ float g_add[(size_t)ROWS * 4096];
__device__ float g_qkv[(size_t)ROWS * 6144];
__device__ float g_invf[64];

__device__ __nv_bfloat16 g_Ahi[(size_t)ROWS * H_];
__device__ __nv_bfloat16 g_Alo[(size_t)ROWS * H_];
__device__ __nv_bfloat16 g_tsHi[(size_t)ROWS * TS_];
__device__ __nv_bfloat16 g_tsLo[(size_t)ROWS * TS_];
__device__ __nv_bfloat16 g_Qhi[(size_t)ROWS * H_];
__device__ __nv_bfloat16 g_Qlo[(size_t)ROWS * H_];
__device__ __nv_bfloat16 g_Khi[(size_t)ROWS * H_];
__device__ __nv_bfloat16 g_Klo[(size_t)ROWS * H_];
__device__ __nv_bfloat16 g_Vhi[(size_t)ROWS * H_];
__device__ __nv_bfloat16 g_Vlo[(size_t)ROWS * H_];

#define WOFF_Q  ((size_t)0)
#define WOFF_K  ((size_t)4194304)
#define WOFF_V  ((size_t)8388608)
#define WOFF_O  ((size_t)12582912)
#define WOFF_TS ((size_t)16777216)
#define WOFF_OR ((size_t)17825792)
#define WTOTAL  ((size_t)19922944)
__device__ __nv_bfloat16 g_WHi[WTOTAL];
__device__ __nv_bfloat16 g_WLo[WTOTAL];

__global__ void init_invf_kernel() {
    int d = threadIdx.x;
    if (d < 64) g_invf[d] = (float)exp(-(double)d * (9.210340371976184 / 64.0));
}

// ---------------- convert kernels ------------------------------------------
__global__ void convertA_kernel(const float* __restrict__ src,
                                __nv_bfloat16* __restrict__ hi,
                                __nv_bfloat16* __restrict__ lo, int n4)
{
    int i = blockIdx.x * blockDim.x + threadIdx.x;
    if (i >= n4) return;
    float4 v = ((const float4*)src)[i];
    __nv_bfloat16 h0 = __float2bfloat16(v.x);
    __nv_bfloat16 h1 = __float2bfloat16(v.y);
    __nv_bfloat16 h2 = __float2bfloat16(v.z);
    __nv_bfloat16 h3 = __float2bfloat16(v.w);
    __nv_bfloat16 l0 = __float2bfloat16(v.x - __bfloat162float(h0));
    __nv_bfloat16 l1 = __float2bfloat16(v.y - __bfloat162float(h1));
    __nv_bfloat16 l2 = __float2bfloat16(v.z - __bfloat162float(h2));
    __nv_bfloat16 l3 = __float2bfloat16(v.w - __bfloat162float(h3));
    ushort4 hv = make_ushort4(__bfloat16_as_ushort(h0), __bfloat16_as_ushort(h1),
                              __bfloat16_as_ushort(h2), __bfloat16_as_ushort(h3));
    ushort4 lv = make_ushort4(__bfloat16_as_ushort(l0), __bfloat16_as_ushort(l1),
                              __bfloat16_as_ushort(l2), __bfloat16_as_ushort(l3));
    ((ushort4*)hi)[i] = hv;
    ((ushort4*)lo)[i] = lv;
}

__global__ void convertBT_kernel(const float* __restrict__ src, int ld, int Kdim,
                                 __nv_bfloat16* __restrict__ hi,
                                 __nv_bfloat16* __restrict__ lo)
{
    __shared__ float t[32][33];
    int tx = threadIdx.x, ty = threadIdx.y;
    int k0 = blockIdx.x * 32, n0 = blockIdx.y * 32;
    #pragma unroll
    for (int i = 0; i < 4; i++)
        t[ty + 8 * i][tx] = src[(size_t)(k0 + ty + 8 * i) * ld + n0 + tx];
    __syncthreads();
    #pragma unroll
    for (int i = 0; i < 4; i++) {
        float v = t[tx][ty + 8 * i];
        __nv_bfloat16 h = __float2bfloat16(v);
        __nv_bfloat16 l = __float2bfloat16(v - __bfloat162float(h));
        size_t o = (size_t)(n0 + ty + 8 * i) * Kdim + k0 + tx;
        hi[o] = h; lo[o] = l;
    }
}

// ============= 128x128 HMMA GEMM (2-stage) — used for the small ts GEMM ====
#define LDT    40
#define PLSZ   (128*LDT*2)
#define BUFSZ  (4*PLSZ)
#define GEMM_SMEM (2*BUFSZ)

__global__ __launch_bounds__(256) void gemm_mma(
    const __nv_bfloat16* __restrict__ Ahi, const __nv_bfloat16* __restrict__ Alo,
    const __nv_bfloat16* __restrict__ Bhi, const __nv_bfloat16* __restrict__ Blo,
    const float* __restrict__ Add, float* __restrict__ C,
    int K, int N, int ldadd)
{
    extern __shared__ char smc[];
    uint32_t sb = smem_u32(smc);
    int tid = threadIdx.x, lane = tid & 31, wid = tid >> 5;
    int wm = wid >> 2, wn = wid & 3;
    int tile_n = blockIdx.x * 128, tile_m = blockIdx.y * 128;

    int lrow = tid & 127, plane = tid >> 7;
    const uint4* Ag = (const uint4*)((plane ? Alo : Ahi) + (size_t)(tile_m + lrow) * K);
    const uint4* Bg = (const uint4*)((plane ? Blo : Bhi) + (size_t)(tile_n + lrow) * K);
    uint32_t dstA = sb + plane * PLSZ + lrow * (LDT * 2);
    uint32_t dstB = dstA + 2 * PLSZ;

    float acc[4][4][4];
    #pragma unroll
    for (int i = 0; i < 4; i++)
        #pragma unroll
        for (int j = 0; j < 4; j++)
            #pragma unroll
            for (int e = 0; e < 4; e++) acc[i][j][e] = 0.f;

    int nch = K >> 5;
    #pragma unroll
    for (int j = 0; j < 4; j++) {
        cpa16(dstA + j * 16, Ag + j);
        cpa16(dstB + j * 16, Bg + j);
    }
    CPA_COMMIT();
    #pragma unroll
    for (int j = 0; j < 4; j++) {
        cpa16(dstA + BUFSZ + j * 16, Ag + 4 + j);
        cpa16(dstB + BUFSZ + j * 16, Bg + 4 + j);
    }
    CPA_COMMIT();

    for (int c = 0; c < nch; c++) {
        if (c + 1 < nch) { CPA_WAIT1(); } else { CPA_WAIT0(); }
        __syncthreads();

        uint32_t base = sb + (c & 1) * BUFSZ;
        #pragma unroll
        for (int s = 0; s < 2; s++) {
            uint32_t bh[4][2], bl[4][2];
            #pragma unroll
            for (int jp = 0; jp < 2; jp++) {
                uint32_t nloc = (uint32_t)(wn * 32 + jp * 16 + ((lane >> 4) & 1) * 8 + (lane & 7));
                uint32_t off = nloc * 80 + s * 32 + ((lane >> 3) & 1) * 16;
                uint32_t t[4];
                ldsm4(t, base + 2 * PLSZ + off);
                bh[jp * 2][0] = t[0]; bh[jp * 2][1] = t[1];
                bh[jp * 2 + 1][0] = t[2]; bh[jp * 2 + 1][1] = t[3];
                ldsm4(t, base + 3 * PLSZ + off);
                bl[jp * 2][0] = t[0]; bl[jp * 2][1] = t[1];
                bl[jp * 2 + 1][0] = t[2]; bl[jp * 2 + 1][1] = t[3];
            }
            #pragma unroll
            for (int i = 0; i < 4; i++) {
                uint32_t ra = (uint32_t)(wm * 64 + i * 16 + (lane & 7) + ((lane >> 3) & 1) * 8) * 80
                            + s * 32 + ((lane >> 4) & 1) * 16;
                uint32_t ah[4], al[4];
                ldsm4(ah, base + ra);
                ldsm4(al, base + PLSZ + ra);
                #pragma unroll
                for (int j = 0; j < 4; j++) {
                    mma16816(acc[i][j], ah, bh[j]);
                    mma16816(acc[i][j], al, bh[j]);
                    mma16816(acc[i][j], ah, bl[j]);
                }
            }
        }
        __syncthreads();

        if (c + 2 < nch) {
            uint32_t dA = dstA + (c & 1) * BUFSZ;
            uint32_t dB = dstB + (c & 1) * BUFSZ;
            const uint4* a = Ag + (size_t)(c + 2) * 4;
            const uint4* b = Bg + (size_t)(c + 2) * 4;
            #pragma unroll
            for (int j = 0; j < 4; j++) {
                cpa16(dA + j * 16, a + j);
                cpa16(dB + j * 16, b + j);
            }
            CPA_COMMIT();
        }
    }

    int addn = (tile_n >= 4096) ? tile_n - 2048 : tile_n;
    #pragma unroll
    for (int i = 0; i < 4; i++) {
        int row = tile_m + wm * 64 + i * 16 + (lane >> 2);
        #pragma unroll
        for (int j = 0; j < 4; j++) {
            int loc = wn * 32 + j * 8 + (lane & 3) * 2;
            float2 v0 = make_float2(acc[i][j][0], acc[i][j][1]);
            float2 v1 = make_float2(acc[i][j][2], acc[i][j][3]);
            if (Add) {
                float2 a0 = *(const float2*)&Add[(size_t)row * ldadd + addn + loc];
                float2 a1 = *(const float2*)&Add[(size_t)(row + 8) * ldadd + addn + loc];
                v0.x += a0.x; v0.y += a0.y;
                v1.x += a1.x; v1.y += a1.y;
            }
            *(float2*)&C[(size_t)row * N + tile_n + loc] = v0;
            *(float2*)&C[(size_t)(row + 8) * N + tile_n + loc] = v1;
        }
    }
}

// ============= 256x128 HMMA GEMM, 3-stage cp.async, single sync ============
// stage layout: AHi[0,20480) ALo[20480,40960) BHi[40960,51200) BLo[51200,61440)
#define STG256   61440
#define GEMM_SMEM256 (3*STG256)      // 184320

__global__ __launch_bounds__(256) void gemm256(
    const __nv_bfloat16* __restrict__ Ahi, const __nv_bfloat16* __restrict__ Alo,
    const __nv_bfloat16* __restrict__ Bhi, const __nv_bfloat16* __restrict__ Blo,
    const float* __restrict__ Add, float* __restrict__ C,
    int K, int N, int ldadd)
{
    extern __shared__ char smc[];
    uint32_t sb = smem_u32(smc);
    int tid = threadIdx.x, lane = tid & 31, wid = tid >> 5;
    int wm = wid >> 1, wn = wid & 1;            // 4x2 warps, warp tile 64x64
    int tile_n = blockIdx.x * 128, tile_m = blockIdx.y * 256;

    // loaders
    const uint4* AgHi = (const uint4*)(Ahi + (size_t)(tile_m + tid) * K);
    const uint4* AgLo = (const uint4*)(Alo + (size_t)(tile_m + tid) * K);
    int brow = tid & 127, bplane = tid >> 7;
    const uint4* Bg = (const uint4*)((bplane ? Blo : Bhi) + (size_t)(tile_n + brow) * K);
    uint32_t dA0 = sb + (uint32_t)tid * 80;
    uint32_t dA1 = sb + 20480 + (uint32_t)tid * 80;
    uint32_t dB  = sb + 40960 + (uint32_t)bplane * 10240 + (uint32_t)brow * 80;

    float acc[4][8][4];
    #pragma unroll
    for (int i = 0; i < 4; i++)
        #pragma unroll
        for (int j = 0; j < 8; j++)
            #pragma unroll
            for (int e = 0; e < 4; e++) acc[i][j][e] = 0.f;

    int nch = K >> 5;
    // prologue: chunks 0 and 1 into stages 0,1
    #pragma unroll
    for (int j = 0; j < 4; j++) {
        cpa16(dA0 + j * 16, AgHi + j);
        cpa16(dA1 + j * 16, AgLo + j);
        cpa16(dB  + j * 16, Bg + j);
    }
    CPA_COMMIT();
    #pragma unroll
    for (int j = 0; j < 4; j++) {
        cpa16(dA0 + STG256 + j * 16, AgHi + 4 + j);
        cpa16(dA1 + STG256 + j * 16, AgLo + 4 + j);
        cpa16(dB  + STG256 + j * 16, Bg + 4 + j);
    }
    CPA_COMMIT();

    int st_pf = 2;          // stage to prefetch into
    int st_cp = 0;          // stage to compute from
    for (int c = 0; c < nch; c++) {
        if (c + 1 < nch) { CPA_WAIT1(); } else { CPA_WAIT0(); }
        __syncthreads();

        if (c + 2 < nch) {
            uint32_t o = (uint32_t)st_pf * STG256;
            const uint4* a0 = AgHi + (size_t)(c + 2) * 4;
            const uint4* a1 = AgLo + (size_t)(c + 2) * 4;
            const uint4* b  = Bg   + (size_t)(c + 2) * 4;
            #pragma unroll
            for (int j = 0; j < 4; j++) {
                cpa16(dA0 + o + j * 16, a0 + j);
                cpa16(dA1 + o + j * 16, a1 + j);
                cpa16(dB  + o + j * 16, b + j);
            }
            CPA_COMMIT();
            if (++st_pf == 3) st_pf = 0;
        }

        uint32_t base = sb + (uint32_t)st_cp * STG256;
        if (++st_cp == 3) st_cp = 0;
        #pragma unroll
        for (int s = 0; s < 2; s++) {
            uint32_t ah[4][4], al[4][4];
            #pragma unroll
            for (int i = 0; i < 4; i++) {
                uint32_t ra = (uint32_t)(wm * 64 + i * 16 + (lane & 7) + ((lane >> 3) & 1) * 8) * 80
                            + s * 32 + ((lane >> 4) & 1) * 16;
                ldsm4(ah[i], base + ra);
                ldsm4(al[i], base + 20480 + ra);
            }
            #pragma unroll
            for (int jp = 0; jp < 4; jp++) {
                uint32_t nloc = (uint32_t)(wn * 64 + jp * 16 + ((lane >> 4) & 1) * 8 + (lane & 7));
                uint32_t off = 40960 + nloc * 80 + s * 32 + ((lane >> 3) & 1) * 16;
                uint32_t tb[4], tl[4];
                ldsm4(tb, base + off);
                ldsm4(tl, base + off + 10240);
                #pragma unroll
                for (int i = 0; i < 4; i++) {
                    mma16816(acc[i][jp * 2],     ah[i], tb);
                    mma16816(acc[i][jp * 2],     al[i], tb);
                    mma16816(acc[i][jp * 2],     ah[i], tl);
                    mma16816(acc[i][jp * 2 + 1], ah[i], tb + 2);
                    mma16816(acc[i][jp * 2 + 1], al[i], tb + 2);
                    mma16816(acc[i][jp * 2 + 1], ah[i], tl + 2);
                }
            }
        }
    }

    int addn = (tile_n >= 4096) ? tile_n - 2048 : tile_n;
    #pragma unroll
    for (int i = 0; i < 4; i++) {
        int row = tile_m + wm * 64 + i * 16 + (lane >> 2);
        #pragma unroll
        for (int j = 0; j < 8; j++) {
            int loc = wn * 64 + j * 8 + (lane & 3) * 2;
            float2 v0 = make_float2(acc[i][j][0], acc[i][j][1]);
            float2 v1 = make_float2(acc[i][j][2], acc[i][j][3]);
            if (Add) {
                float2 a0 = *(const float2*)&Add[(size_t)row * ldadd + addn + loc];
                float2 a1 = *(const float2*)&Add[(size_t)(row + 8) * ldadd + addn + loc];
                v0.x += a0.x; v0.y += a0.y;
                v1.x += a1.x; v1.y += a1.y;
            }
            *(float2*)&C[(size_t)row * N + tile_n + loc] = v0;
            *(float2*)&C[(size_t)(row + 8) * N + tile_n + loc] = v1;
        }
    }
}

// -------- blend + rmsnorm + exact k-th + relu-shift; writes bf16 planes ----
__global__ __launch_bounds__(512) void ts_rowops_kernel(
    const float* __restrict__ last, const float* __restrict__ w,
    const float* __restrict__ ts,
    __nv_bfloat16* __restrict__ tsHi, __nv_bfloat16* __restrict__ tsLo)
{
    __shared__ float sv[512];
    __shared__ float rbuf[512];
    int row = blockIdx.x;
    int j = threadIdx.x;
    size_t idx = (size_t)row * TS_ + j;

    float x = 0.5f * ts[idx] + 0.5f * last[idx];
    rbuf[j] = x * x;
    __syncthreads();
    #pragma unroll
    for (int s2 = 256; s2 > 0; s2 >>= 1) {
        if (j < s2) rbuf[j] += rbuf[j + s2];
        __syncthreads();
    }
    float var = rbuf[0] * (1.f / 512.f);
    float y = x * rsqrtf(var + 1e-6f) * w[j];
    sv[j] = y;
    __syncthreads();

    for (int k = 2; k <= 512; k <<= 1) {
        for (int jj = k >> 1; jj > 0; jj >>= 1) {
            int ixj = j ^ jj;
            if (ixj > j) {
                float a = sv[j], b = sv[ixj];
                bool asc = ((j & k) == 0);
                if (asc ? (a > b) : (a < b)) { sv[j] = b; sv[ixj] = a; }
            }
            __syncthreads();
        }
    }
    float kth = sv[KIDX - 1];
    split_store(fmaxf(y - kth, 0.f), tsHi, tsLo, idx);
}

// ------- RoPE + transpose to head-major bf16 hi/lo planes [B,NH,S,HD] ------
__global__ void rope_transpose_kernel(
    const float* __restrict__ qkv,
    __nv_bfloat16* __restrict__ Qhi, __nv_bfloat16* __restrict__ Qlo,
    __nv_bfloat16* __restrict__ Khi, __nv_bfloat16* __restrict__ Klo,
    __nv_bfloat16* __restrict__ Vhi, __nv_bfloat16* __restrict__ Vlo)
{
    int i = blockIdx.x * blockDim.x + threadIdx.x;
    if (i >= ROWS * NH_ * 64) return;
    int d = i & 63;
    int h = (i >> 6) & (NH_ - 1);
    int row = i >> 10;
    int b = row >> 11;
    int s = row & (S_ - 1);

    float inv = g_invf[d];
    float ang = (float)s * inv;
    float cs, sn;
    sincosf(ang, &sn, &cs);

    size_t src = (size_t)row * 6144 + h * HD_ + d;
    float q0 = qkv[src],        q1 = qkv[src + 64];
    float k0 = qkv[src + 2048], k1 = qkv[src + 2048 + 64];
    float v0 = qkv[src + 4096], v1 = qkv[src + 4096 + 64];
    size_t dst = ((size_t)(b * NH_ + h) * S_ + s) * HD_ + d;
    split_store(q0 * cs - q1 * sn, Qhi, Qlo, dst);
    split_store(q1 * cs + q0 * sn, Qhi, Qlo, dst + 64);
    split_store(k0 * cs - k1 * sn, Khi, Klo, dst);
    split_store(k1 * cs + k0 * sn, Khi, Klo, dst + 64);
    split_store(v0, Vhi, Vlo, dst);
    split_store(v1, Vhi, Vlo, dst + 64);
}

// ---------------- flash attention on mma.sync (bf16 split) -----------------
// 128 q-rows/CTA, 8 warps, 64-key tiles.
#define LDB2  272
#define TQH   0
#define TQL   34816
#define TKH   69632
#define TKL   87040
#define TVH   104448
#define TVL   121856
#define FLASH_SMEM2 139264

__global__ __launch_bounds__(256) void flash_mma(
    const __nv_bfloat16* __restrict__ Qhi, const __nv_bfloat16* __restrict__ Qlo,
    const __nv_bfloat16* __restrict__ Khi, const __nv_bfloat16* __restrict__ Klo,
    const __nv_bfloat16* __restrict__ Vhi, const __nv_bfloat16* __restrict__ Vlo,
    __nv_bfloat16* __restrict__ Ohi, __nv_bfloat16* __restrict__ Olo)
{
    extern __shared__ char sm[];
    uint32_t sb = smem_u32(sm);
    int tid = threadIdx.x, l = tid & 31, w = tid >> 5;
    int qt = blockIdx.x, bh = blockIdx.y;
    size_t bhS = (size_t)bh * S_;

    // Q tile: 2 planes x 128 rows x 16 uint4
    for (int i = tid; i < 4096; i += 256) {
        int plane = i >> 11, row = (i >> 4) & 127, c = i & 15;
        const uint4* src = (const uint4*)((plane ? Qlo : Qhi) + (bhS + (size_t)qt * 128 + row) * HD_);
        *(uint4*)(sm + (plane ? TQL : TQH) + row * LDB2 + c * 16) = src[c];
    }

    float o[16][4];
    #pragma unroll
    for (int t = 0; t < 16; t++)
        #pragma unroll
        for (int e = 0; e < 4; e++) o[t][e] = 0.f;
    float m1 = -INFINITY, m2 = -INFINITY, l1 = 0.f, l2 = 0.f;
    const float scale = 0.08838834764831845f;

    int ktmax = 2 * qt + 1;
    for (int kt = 0; kt <= ktmax; kt++) {
        __syncthreads();
        for (int i = tid; i < 4096; i += 256) {
            int plane = i >> 10, rem = i & 1023, row = rem >> 4, c = rem & 15;
            const __nv_bfloat16* bp = (plane == 0) ? Khi : (plane == 1) ? Klo
                                      : (plane == 2) ? Vhi : Vlo;
            const uint4* src = (const uint4*)(bp + (bhS + (size_t)kt * 64 + row) * HD_);
            uint32_t off = (plane == 0) ? TKH : (plane == 1) ? TKL : (plane == 2) ? TVH : TVL;
            *(uint4*)(sm + off + row * LDB2 + c * 16) = src[c];
        }
        __syncthreads();

        float s[8][4];
        #pragma unroll
        for (int t = 0; t < 8; t++)
            #pragma unroll
            for (int e = 0; e < 4; e++) s[t][e] = 0.f;

        #pragma unroll
        for (int kk = 0; kk < 8; kk++) {
            uint32_t ah[4], al[4];
            uint32_t ra = sb + TQH + (uint32_t)(w * 16 + (l & 15)) * LDB2
                        + ((l >> 4) & 1) * 16 + kk * 32;
            ldsm4(ah, ra);
            ldsm4(al, ra + (TQL - TQH));
            #pragma unroll
            for (int g = 0; g < 4; g++) {
                uint32_t bhv[4], blv[4];
                uint32_t rb = sb + TKH
                    + (uint32_t)(16 * g + (l & 7) + ((l >> 4) & 1) * 8) * LDB2
                    + ((l >> 3) & 1) * 16 + kk * 32;
                ldsm4(bhv, rb);
                ldsm4(blv, rb + (TKL - TKH));
                mma16816(s[2 * g],     ah, bhv);
                mma16816(s[2 * g],     al, bhv);
                mma16816(s[2 * g],     ah, blv);
                mma16816(s[2 * g + 1], ah, bhv + 2);
                mma16816(s[2 * g + 1], al, bhv + 2);
                mma16816(s[2 * g + 1], ah, blv + 2);
            }
        }

        int r1 = qt * 128 + w * 16 + (l >> 2), r2 = r1 + 8;
        int cb = (kt << 6) + ((l & 3) << 1);
        if (kt >= 2 * qt) {
            #pragma unroll
            for (int t = 0; t < 8; t++) {
                int c0 = cb + t * 8, c1 = c0 + 1;
                s[t][0] = (c0 <= r1) ? s[t][0] * scale : -1e30f;
                s[t][1] = (c1 <= r1) ? s[t][1] * scale : -1e30f;
                s[t][2] = (c0 <= r2) ? s[t][2] * scale : -1e30f;
                s[t][3] = (c1 <= r2) ? s[t][3] * scale : -1e30f;
            }
        } else {
            #pragma unroll
            for (int t = 0; t < 8; t++)
                #pragma unroll
                for (int e = 0; e < 4; e++) s[t][e] *= scale;
        }

        float rm1 = -INFINITY, rm2 = -INFINITY;
        #pragma unroll
        for (int t = 0; t < 8; t++) {
            rm1 = fmaxf(rm1, fmaxf(s[t][0], s[t][1]));
            rm2 = fmaxf(rm2, fmaxf(s[t][2], s[t][3]));
        }
        rm1 = fmaxf(rm1, __shfl_xor_sync(0xffffffffu, rm1, 1));
        rm1 = fmaxf(rm1, __shfl_xor_sync(0xffffffffu, rm1, 2));
        rm2 = fmaxf(rm2, __shfl_xor_sync(0xffffffffu, rm2, 1));
        rm2 = fmaxf(rm2, __shfl_xor_sync(0xffffffffu, rm2, 2));
        float mn1 = fmaxf(m1, rm1), mn2 = fmaxf(m2, rm2);
        float cr1 = __expf(m1 - mn1), cr2 = __expf(m2 - mn2);
        m1 = mn1; m2 = mn2;
        float rs1 = 0.f, rs2 = 0.f;
        #pragma unroll
        for (int t = 0; t < 8; t++) {
            s[t][0] = __expf(s[t][0] - mn1);
            s[t][1] = __expf(s[t][1] - mn1);
            s[t][2] = __expf(s[t][2] - mn2);
            s[t][3] = __expf(s[t][3] - mn2);
            rs1 += s[t][0] + s[t][1];
            rs2 += s[t][2] + s[t][3];
        }
        rs1 += __shfl_xor_sync(0xffffffffu, rs1, 1);
        rs1 += __shfl_xor_sync(0xffffffffu, rs1, 2);
        rs2 += __shfl_xor_sync(0xffffffffu, rs2, 1);
        rs2 += __shfl_xor_sync(0xffffffffu, rs2, 2);
        l1 = l1 * cr1 + rs1;
        l2 = l2 * cr2 + rs2;
        #pragma unroll
        for (int t = 0; t < 16; t++) {
            o[t][0] *= cr1; o[t][1] *= cr1;
            o[t][2] *= cr2; o[t][3] *= cr2;
        }

        #pragma unroll
        for (int t = 0; t < 4; t++) {
            uint32_t pah[4], pal[4];
            float* s0 = s[2 * t];
            float* s1 = s[2 * t + 1];
            pah[0] = pack_bf16(s0[0], s0[1]);
            pah[1] = pack_bf16(s0[2], s0[3]);
            pah[2] = pack_bf16(s1[0], s1[1]);
            pah[3] = pack_bf16(s1[2], s1[3]);
            float q00 = s0[0] - __bfloat162float(__ushort_as_bfloat16((unsigned short)(pah[0] & 0xffff)));
            float q01 = s0[1] - __bfloat162float(__ushort_as_bfloat16((unsigned short)(pah[0] >> 16)));
            float q02 = s0[2] - __bfloat162float(__ushort_as_bfloat16((unsigned short)(pah[1] & 0xffff)));
            float q03 = s0[3] - __bfloat162float(__ushort_as_bfloat16((unsigned short)(pah[1] >> 16)));
            float q10 = s1[0] - __bfloat162float(__ushort_as_bfloat16((unsigned short)(pah[2] & 0xffff)));
            float q11 = s1[1] - __bfloat162float(__ushort_as_bfloat16((unsigned short)(pah[2] >> 16)));
            float q12 = s1[2] - __bfloat162float(__ushort_as_bfloat16((unsigned short)(pah[3] & 0xffff)));
            float q13 = s1[3] - __bfloat162float(__ushort_as_bfloat16((unsigned short)(pah[3] >> 16)));
            pal[0] = pack_bf16(q00, q01);
            pal[1] = pack_bf16(q02, q03);
            pal[2] = pack_bf16(q10, q11);
            pal[3] = pack_bf16(q12, q13);

            #pragma unroll
            for (int g = 0; g < 8; g++) {
                uint32_t bhv[4], blv[4];
                uint32_t rb = sb + TVH
                    + (uint32_t)(16 * t + (l & 7) + ((l >> 3) & 1) * 8) * LDB2
                    + 32 * g + ((l >> 4) & 1) * 16;
                ldsm4t(bhv, rb);
                ldsm4t(blv, rb + (TVL - TVH));
                mma16816(o[2 * g],     pah, bhv);
                mma16816(o[2 * g],     pal, bhv);
                mma16816(o[2 * g],     pah, blv);
                mma16816(o[2 * g + 1], pah, bhv + 2);
                mma16816(o[2 * g + 1], pal, bhv + 2);
                mma16816(o[2 * g + 1], pah, blv + 2);
            }
        }
    }

    float il1 = 1.f / l1, il2 = 1.f / l2;
    int b = bh >> 4, h = bh & (NH_ - 1);
    int sr = qt * 128 + w * 16 + (l >> 2);
    size_t base1 = ((size_t)(b * S_ + sr)) * H_ + h * HD_;
    size_t base2 = base1 + (size_t)8 * H_;
    #pragma unroll
    for (int t = 0; t < 16; t++) {
        int d = t * 8 + (l & 3) * 2;
        float v0 = o[t][0] * il1, v1 = o[t][1] * il1;
        float v2 = o[t][2] * il2, v3 = o[t][3] * il2;
        uint32_t h0 = pack_bf16(v0, v1);
        float w0 = v0 - __bfloat162float(__ushort_as_bfloat16((unsigned short)(h0 & 0xffff)));
        float w1 = v1 - __bfloat162float(__ushort_as_bfloat16((unsigned short)(h0 >> 16)));
        uint32_t h1 = pack_bf16(v2, v3);
        float w2 = v2 - __bfloat162float(__ushort_as_bfloat16((unsigned short)(h1 & 0xffff)));
        float w3 = v3 - __bfloat162float(__ushort_as_bfloat16((unsigned short)(h1 >> 16)));
        *(uint32_t*)&Ohi[base1 + d] = h0;
        *(uint32_t*)&Olo[base1 + d] = pack_bf16(w0, w1);
        *(uint32_t*)&Ohi[base2 + d] = h1;
        *(uint32_t*)&Olo[base2 + d] = pack_bf16(w2, w3);
    }
}

// ---------------------------------------------------------------------------
extern "C" void kernel_launch(void* const* d_in, const int* in_sizes, int n_in,
                              void* d_out, int out_size)
{
    const float* hidden = (const float*)d_in[0];
    const float* lastts = (const float*)d_in[1];
    const float* Wq     = (const float*)d_in[2];
    const float* Wk     = (const float*)d_in[3];
    const float* Wv     = (const float*)d_in[4];
    const float* Wo     = (const float*)d_in[5];
    const float* Wts    = (const float*)d_in[6];
    const float* tsw    = (const float*)d_in[7];
    const float* Worig  = (const float*)d_in[8];
    float* out = (float*)d_out;

    float *ts, *add, *qkv;
    __nv_bfloat16 *Ahi, *Alo, *tsHi, *tsLo, *WHi, *WLo;
    __nv_bfloat16 *Qhi, *Qlo, *Khi, *Klo, *Vhi, *Vlo;
    cudaGetSymbolAddress((void**)&ts,   g_ts);
    cudaGetSymbolAddress((void**)&add,  g_add);
    cudaGetSymbolAddress((void**)&qkv,  g_qkv);
    cudaGetSymbolAddress((void**)&Ahi,  g_Ahi);
    cudaGetSymbolAddress((void**)&Alo,  g_Alo);
    cudaGetSymbolAddress((void**)&tsHi, g_tsHi);
    cudaGetSymbolAddress((void**)&tsLo, g_tsLo);
    cudaGetSymbolAddress((void**)&WHi,  g_WHi);
    cudaGetSymbolAddress((void**)&WLo,  g_WLo);
    cudaGetSymbolAddress((void**)&Qhi,  g_Qhi);
    cudaGetSymbolAddress((void**)&Qlo,  g_Qlo);
    cudaGetSymbolAddress((void**)&Khi,  g_Khi);
    cudaGetSymbolAddress((void**)&Klo,  g_Klo);
    cudaGetSymbolAddress((void**)&Vhi,  g_Vhi);
    cudaGetSymbolAddress((void**)&Vlo,  g_Vlo);

    cudaFuncSetAttribute(gemm_mma, cudaFuncAttributeMaxDynamicSharedMemorySize, GEMM_SMEM);
    cudaFuncSetAttribute(gemm256, cudaFuncAttributeMaxDynamicSharedMemorySize, GEMM_SMEM256);
    cudaFuncSetAttribute(flash_mma, cudaFuncAttributeMaxDynamicSharedMemorySize, FLASH_SMEM2);

    dim3 tb(32, 8);
    convertA_kernel<<<(ROWS * H_ / 4 + 255) / 256, 256>>>(hidden, Ahi, Alo, ROWS * H_ / 4);
    convertBT_kernel<<<dim3(64, 16), tb>>>(Wts, 512, 2048, WHi + WOFF_TS, WLo + WOFF_TS);
    gemm_mma<<<dim3(4, 32), 256, GEMM_SMEM>>>(Ahi, Alo, WHi + WOFF_TS, WLo + WOFF_TS,
                                              nullptr, ts, 2048, 512, 0);
    ts_rowops_kernel<<<ROWS, 512>>>(lastts, tsw, ts, tsHi, tsLo);
    convertBT_kernel<<<dim3(16, 128), tb>>>(Worig, 6144, 512, WHi + WOFF_OR, WLo + WOFF_OR);
    // origin GEMM: M=4096 N=4096 K=512
    gemm256<<<dim3(32, 16), 256, GEMM_SMEM256>>>(tsHi, tsLo, WHi + WOFF_OR, WLo + WOFF_OR,
                                                 nullptr, add, 512, 4096, 0);
    init_invf_kernel<<<1, 64>>>();
    convertBT_kernel<<<dim3(64, 64), tb>>>(Wq, 2048, 2048, WHi + WOFF_Q, WLo + WOFF_Q);
    convertBT_kernel<<<dim3(64, 64), tb>>>(Wk, 2048, 2048, WHi + WOFF_K, WLo + WOFF_K);
    convertBT_kernel<<<dim3(64, 64), tb>>>(Wv, 2048, 2048, WHi + WOFF_V, WLo + WOFF_V);
    // fused QKV GEMM: M=4096 N=6144 K=2048, Add column-wrapped
    gemm256<<<dim3(48, 16), 256, GEMM_SMEM256>>>(Ahi, Alo, WHi + WOFF_Q, WLo + WOFF_Q,
                                                 add, qkv, 2048, 6144, 4096);
    int tot = ROWS * NH_ * 64;
    rope_transpose_kernel<<<(tot + 255) / 256, 256>>>(qkv, Qhi, Qlo, Khi, Klo, Vhi, Vlo);
    flash_mma<<<dim3(S_ / 128, B_ * NH_), 256, FLASH_SMEM2>>>(Qhi, Qlo, Khi, Klo, Vhi, Vlo,
                                                              Ahi, Alo);
    convertBT_kernel<<<dim3(64, 64), tb>>>(Wo, 2048, 2048, WHi + WOFF_O, WLo + WOFF_O);
    gemm256<<<dim3(16, 16), 256, GEMM_SMEM256>>>(Ahi, Alo, WHi + WOFF_O, WLo + WOFF_O,
                                                 nullptr, out, 2048, 2048, 0);
}